// round 2
// baseline (speedup 1.0000x reference)
#include <cuda_runtime.h>
#include <math.h>

// Scratch (static __device__ per allocation rules)
__device__ float g_u[4096 * 1024];      // [N][v_word(512) | v_wch(512)]
__device__ float g_wc[1024 * 1024];     // repacked conv_sent_w[:,:,1]
__device__ float g_pmax[32 * 1024];     // per-nblock column max of r
__device__ float g_h[2048];             // tanh(lin1)

// ---------------- f32x2 packed helpers ----------------
__device__ __forceinline__ unsigned long long pack2(float lo, float hi) {
    unsigned long long r;
    asm("mov.b64 %0, {%1,%2};" : "=l"(r) : "f"(lo), "f"(hi));
    return r;
}
__device__ __forceinline__ void unpack2(unsigned long long v, float& lo, float& hi) {
    asm("mov.b64 {%0,%1}, %2;" : "=f"(lo), "=f"(hi) : "l"(v));
}
__device__ __forceinline__ unsigned long long ffma2(unsigned long long a,
                                                    unsigned long long b,
                                                    unsigned long long c) {
    unsigned long long d;
    asm("fma.rn.f32x2 %0, %1, %2, %3;" : "=l"(d) : "l"(a), "l"(b), "l"(c));
    return d;
}
// {hi(a), lo(b)}
__device__ __forceinline__ unsigned long long mid2(unsigned long long a,
                                                   unsigned long long b) {
    unsigned long long r;
    asm("{\n\t.reg .b32 al, ah, bl, bh;\n\t"
        "mov.b64 {al,ah}, %1;\n\t"
        "mov.b64 {bl,bh}, %2;\n\t"
        "mov.b64 %0, {ah,bl};\n\t}"
        : "=l"(r) : "l"(a), "l"(b));
    return r;
}

// ---------------------------------------------------------------------------
// A: v_word gather (padding_idx=0 -> zero row)
// ---------------------------------------------------------------------------
__global__ void k_word(const int* __restrict__ words, const float* __restrict__ we) {
    int n = blockIdx.x;
    int w = words[n];
    float4 v = make_float4(0.f, 0.f, 0.f, 0.f);
    if (w != 0) v = ((const float4*)(we + (size_t)w * 512))[threadIdx.x];
    ((float4*)(g_u + (size_t)n * 1024))[threadIdx.x] = v;
}

// ---------------------------------------------------------------------------
// B: char conv (512->512, k=3, pad=1, L=32) + maxpool -> u right half
// CTA: 4 words x 128 out-channels. K loop: 32 chunks of 16 in-channels.
// f32x2 packed over position pairs; weights pre-duplicated {w,w} in SMEM.
// Dynamic SMEM layout:
//   [0, 9248)          Xs  : 4 groups x 16 rows x 34 floats (halo at 0/33)
//   [0, 8704)          red : overlays Xs after main loop
//   [9248, 58400)      Ws2 : 128 oc x 48 (a*3+k) as {w,w} ull pairs
//   [58400, 58912)     cs  : 4x32 char ids
// ---------------------------------------------------------------------------
#define CONV_SMEM_BYTES 58912

__global__ __launch_bounds__(256, 2) void k_conv(
    const int* __restrict__ wic, const float* __restrict__ ce,
    const float* __restrict__ cw, const float* __restrict__ cb) {
    extern __shared__ char smem_raw[];
    float* Xs = (float*)smem_raw;                                   // 4*578
    unsigned long long* Ws2 = (unsigned long long*)(smem_raw + 9248); // [128][48]
    float* red = (float*)smem_raw;                                  // overlay
    int* cs = (int*)(smem_raw + 58400);                             // [4][32]

    int t   = threadIdx.x;
    int nb  = blockIdx.x * 4;
    int oc0 = blockIdx.y * 128;

    if (t < 128) cs[t] = wic[nb * 32 + t];
    for (int i = t; i < 64; i += 256) {
        int g = i >> 4, a = i & 15;
        Xs[g * 578 + a * 34 + 0]  = 0.f;
        Xs[g * 578 + a * 34 + 33] = 0.f;
    }

    int tx = t & 15, ty = t >> 4;
    int g  = tx >> 2;
    int l0 = (tx & 3) * 8;                 // even -> 8B-aligned pair base
    const float* Xg = Xs + g * 578;

    unsigned long long acc[8][4];
#pragma unroll
    for (int i = 0; i < 8; i++)
#pragma unroll
        for (int j = 0; j < 4; j++) acc[i][j] = 0ull;

    __syncthreads();

    for (int chunk = 0; chunk < 32; chunk++) {
        // load X: 4 words x 512 floats (one char-emb row each)
#pragma unroll
        for (int j = 0; j < 8; j++) {
            int i  = t + j * 256;            // 0..2047
            int gg = i >> 9, d = i & 511;
            int c  = cs[gg * 32 + chunk];
            float v = (c == 0) ? 0.f : ce[c * 512 + d];
            Xs[gg * 578 + (d >> 5) * 34 + 1 + (d & 31)] = v;
        }
        // load W duplicated: 128 oc x 16 ic x 3 taps -> {w,w}
#pragma unroll
        for (int j = 0; j < 24; j++) {
            int i = t + j * 256;             // 0..6143
            int o = i / 48, r = i - o * 48;
            float w = cw[(size_t)(oc0 + o) * 1536 + chunk * 48 + r];
            Ws2[o * 48 + r] = pack2(w, w);
        }
        __syncthreads();

#pragma unroll 2
        for (int a = 0; a < 16; a++) {
            // 5 aligned LDS.64: e[j] = {x[l0-1+2j], x[l0+2j]}
            const unsigned long long* Xp =
                (const unsigned long long*)(Xg + a * 34 + l0);
            unsigned long long e[5];
#pragma unroll
            for (int j = 0; j < 5; j++) e[j] = Xp[j];
            unsigned long long m[4];
#pragma unroll
            for (int c = 0; c < 4; c++) m[c] = mid2(e[c], e[c + 1]);

#pragma unroll
            for (int oo = 0; oo < 8; oo++) {
                const unsigned long long* wr = Ws2 + (ty * 8 + oo) * 48 + a * 3;
                unsigned long long w0 = wr[0], w1 = wr[1], w2 = wr[2];
#pragma unroll
                for (int c = 0; c < 4; c++) {
                    acc[oo][c] = ffma2(w0, e[c], acc[oo][c]);      // tap 0
                    acc[oo][c] = ffma2(w1, m[c], acc[oo][c]);      // tap 1
                    acc[oo][c] = ffma2(w2, e[c + 1], acc[oo][c]);  // tap 2
                }
            }
        }
        __syncthreads();
    }

    // maxpool over positions (8 per thread), then across 4 threads/word
#pragma unroll
    for (int oo = 0; oo < 8; oo++) {
        float mlo, mhi, a0, a1;
        unpack2(acc[oo][0], mlo, mhi);
        float mm = fmaxf(mlo, mhi);
#pragma unroll
        for (int c = 1; c < 4; c++) {
            unpack2(acc[oo][c], a0, a1);
            mm = fmaxf(mm, fmaxf(a0, a1));
        }
        red[(ty * 8 + oo) * 17 + tx] = mm;
    }
    __syncthreads();
    for (int i = t; i < 512; i += 256) {
        int gg = i >> 7, o = i & 127;
        const float* rp = red + o * 17 + gg * 4;
        float mm = fmaxf(fmaxf(rp[0], rp[1]), fmaxf(rp[2], rp[3]));
        g_u[(size_t)(nb + gg) * 1024 + 512 + oc0 + o] = mm + cb[oc0 + o];
    }
}

// ---------------------------------------------------------------------------
// C1: repack conv_sent_w center tap -> dense [1024][1024]
// ---------------------------------------------------------------------------
__global__ void k_repack(const float* __restrict__ ws) {
    int i = blockIdx.x * 256 + threadIdx.x;
    g_wc[i] = ws[(size_t)i * 3 + 1];
}

// ---------------------------------------------------------------------------
// C2: r = u @ Wc^T + b, fused per-CTA column max -> g_pmax[nblk][1024]
// ---------------------------------------------------------------------------
__global__ __launch_bounds__(256, 2) void k_sent(const float* __restrict__ csb) {
    __shared__ float Us[32 * 129];
    __shared__ float Wss[32 * 129];
    __shared__ float red[128 * 17];
    int t  = threadIdx.x;
    int nb = blockIdx.x * 128;
    int o0 = blockIdx.y * 128;
    int tx = t & 15, ty = t >> 4;

    float acc[8][8];
#pragma unroll
    for (int i = 0; i < 8; i++)
#pragma unroll
        for (int j = 0; j < 8; j++) acc[i][j] = 0.f;

    for (int i0 = 0; i0 < 1024; i0 += 32) {
#pragma unroll
        for (int j = 0; j < 16; j++) {
            int i = t + j * 256;
            int n = i >> 5, k = i & 31;
            Us[k * 129 + n]  = g_u[(size_t)(nb + n) * 1024 + i0 + k];
            Wss[k * 129 + n] = g_wc[(size_t)(o0 + n) * 1024 + i0 + k];
        }
        __syncthreads();
#pragma unroll 4
        for (int k = 0; k < 32; k++) {
            float xv[8], wv[8];
#pragma unroll
            for (int nn = 0; nn < 8; nn++) xv[nn] = Us[k * 129 + tx + nn * 16];
#pragma unroll
            for (int oo = 0; oo < 8; oo++) wv[oo] = Wss[k * 129 + ty * 8 + oo];
#pragma unroll
            for (int oo = 0; oo < 8; oo++)
#pragma unroll
                for (int nn = 0; nn < 8; nn++)
                    acc[oo][nn] = fmaf(wv[oo], xv[nn], acc[oo][nn]);
        }
        __syncthreads();
    }

#pragma unroll
    for (int oo = 0; oo < 8; oo++) {
        float m = acc[oo][0];
#pragma unroll
        for (int nn = 1; nn < 8; nn++) m = fmaxf(m, acc[oo][nn]);
        red[(ty * 8 + oo) * 17 + tx] = m;
    }
    __syncthreads();
    if (t < 128) {
        float m = red[t * 17];
#pragma unroll
        for (int j = 1; j < 16; j++) m = fmaxf(m, red[t * 17 + j]);
        g_pmax[blockIdx.x * 1024 + o0 + t] = m + csb[o0 + t];
    }
}

// ---------------------------------------------------------------------------
// D2: final max over 32 partials, then lin1+tanh
// ---------------------------------------------------------------------------
__global__ void k_lin1(const float* __restrict__ w1, const float* __restrict__ b1) {
    __shared__ float rm[1024];
    int t = threadIdx.x;   // 128
    for (int o = t; o < 1024; o += 128) {
        float m = g_pmax[o];
#pragma unroll
        for (int j = 1; j < 32; j++) m = fmaxf(m, g_pmax[j * 1024 + o]);
        rm[o] = m;
    }
    __syncthreads();
    int j = blockIdx.x * 128 + t;
    float s = b1[j];
    const float* wr = w1 + (size_t)j * 1024;
    for (int i = 0; i < 1024; i++) s = fmaf(rm[i], wr[i], s);
    g_h[j] = tanhf(s);
}

// ---------------------------------------------------------------------------
// D3: out = h @ lin2_w^T + lin2_b  -> [2]
// ---------------------------------------------------------------------------
__global__ void k_lin2(const float* __restrict__ w2, const float* __restrict__ b2,
                       float* __restrict__ out) {
    __shared__ float p0s[256], p1s[256];
    int t = threadIdx.x;
    float p0 = 0.f, p1 = 0.f;
    for (int i = t; i < 2048; i += 256) {
        float h = g_h[i];
        p0 = fmaf(h, w2[i], p0);
        p1 = fmaf(h, w2[2048 + i], p1);
    }
    p0s[t] = p0; p1s[t] = p1;
    __syncthreads();
    for (int s = 128; s > 0; s >>= 1) {
        if (t < s) { p0s[t] += p0s[t + s]; p1s[t] += p1s[t + s]; }
        __syncthreads();
    }
    if (t == 0) { out[0] = p0s[0] + b2[0]; out[1] = p1s[0] + b2[1]; }
}

// ---------------------------------------------------------------------------
extern "C" void kernel_launch(void* const* d_in, const int* in_sizes, int n_in,
                              void* d_out, int out_size) {
    const int*   words = (const int*)d_in[0];
    const int*   wic   = (const int*)d_in[1];
    const float* we    = (const float*)d_in[2];
    const float* ce    = (const float*)d_in[3];
    const float* cw    = (const float*)d_in[4];
    const float* cb    = (const float*)d_in[5];
    const float* ws    = (const float*)d_in[6];
    const float* csb   = (const float*)d_in[7];
    const float* w1    = (const float*)d_in[8];
    const float* b1    = (const float*)d_in[9];
    const float* w2    = (const float*)d_in[10];
    const float* b2    = (const float*)d_in[11];
    float* out = (float*)d_out;

    static int smem_set = 0;
    if (!smem_set) {
        cudaFuncSetAttribute(k_conv, cudaFuncAttributeMaxDynamicSharedMemorySize,
                             CONV_SMEM_BYTES);
        smem_set = 1;
    }

    k_word  <<<4096, 128>>>(words, we);
    k_repack<<<4096, 256>>>(ws);
    k_conv  <<<dim3(1024, 4), 256, CONV_SMEM_BYTES>>>(wic, ce, cw, cb);
    k_sent  <<<dim3(32, 8), 256>>>(csb);
    k_lin1  <<<16, 128>>>(w1, b1);
    k_lin2  <<<1, 256>>>(w2, b2, out);
}

// round 5
// speedup vs baseline: 3.2887x; 3.2887x over previous
#include <cuda_runtime.h>
#include <cuda_bf16.h>
#include <stdint.h>
#include <math.h>

// ---------------------------------------------------------------- scratch
__device__ float g_u[4096 * 1024];      // [N][v_word(512) | v_wch(512)]
__device__ float g_wc[1024 * 1024];     // repacked conv_sent_w[:,:,1]
__device__ float g_pmax[32 * 1024];
__device__ float g_h[2048];
__device__ __nv_bfloat16 g_ceh[256 * 512];   // char emb transposed, hi split
__device__ __nv_bfloat16 g_cel[256 * 512];   // lo split
// prepacked conv weights: [og(4)][chunk(32)] blocks of 36864B
//   block = [tap(3)][spl(2)][oc(128)] rows of 48B (16 bf16 data + pad)
__device__ uint4 g_wA4[4 * 32 * 36864 / 16];

// ---------------------------------------------------------------- helpers
__device__ __forceinline__ uint32_t smem_u32(const void* p) {
    uint32_t a;
    asm("{ .reg .u64 t; cvta.to.shared.u64 t, %1; cvt.u32.u64 %0, t; }"
        : "=r"(a) : "l"(p));
    return a;
}
__device__ __forceinline__ void cp16(uint32_t dst, const void* src) {
    asm volatile("cp.async.cg.shared.global [%0], [%1], 16;"
                 :: "r"(dst), "l"(src) : "memory");
}
__device__ __forceinline__ void cp_commit() {
    asm volatile("cp.async.commit_group;" ::: "memory");
}
__device__ __forceinline__ void cp_wait0() {
    asm volatile("cp.async.wait_group 0;" ::: "memory");
}
__device__ __forceinline__ void cp_wait1() {
    asm volatile("cp.async.wait_group 1;" ::: "memory");
}
__device__ __forceinline__ void ldsm_x4(uint32_t* r, uint32_t addr) {
    asm volatile("ldmatrix.sync.aligned.m8n8.x4.shared.b16 {%0,%1,%2,%3}, [%4];"
                 : "=r"(r[0]), "=r"(r[1]), "=r"(r[2]), "=r"(r[3]) : "r"(addr));
}
__device__ __forceinline__ void ldsm_x2(uint32_t* r, uint32_t addr) {
    asm volatile("ldmatrix.sync.aligned.m8n8.x2.shared.b16 {%0,%1}, [%2];"
                 : "=r"(r[0]), "=r"(r[1]) : "r"(addr));
}
__device__ __forceinline__ void mma16816(float* c, const uint32_t* a, const uint32_t* b) {
    asm volatile(
        "mma.sync.aligned.m16n8k16.row.col.f32.bf16.bf16.f32 "
        "{%0,%1,%2,%3}, {%4,%5,%6,%7}, {%8,%9}, {%0,%1,%2,%3};"
        : "+f"(c[0]), "+f"(c[1]), "+f"(c[2]), "+f"(c[3])
        : "r"(a[0]), "r"(a[1]), "r"(a[2]), "r"(a[3]), "r"(b[0]), "r"(b[1]));
}

// ---------------------------------------------------------------- prepacks
// char emb -> transposed + hi/lo split: g_ce*[c][pos*16 + r] = ce[c][r*32+pos]
__global__ void k_prep_ce(const float* __restrict__ ce) {
    int c = blockIdx.x;
    for (int d = threadIdx.x; d < 512; d += 256) {
        float v = (c == 0) ? 0.f : ce[c * 512 + d];
        __nv_bfloat16 h = __float2bfloat16(v);
        float lo = v - __bfloat162float(h);
        int idx = c * 512 + (d & 31) * 16 + (d >> 5);
        g_ceh[idx] = h;
        g_cel[idx] = __float2bfloat16(lo);
    }
}

// conv weights -> [og][chunk] 36864B blocks: [tap][spl][oc128] rows of 24 bf16
__global__ void k_prep_w(const float* __restrict__ cw) {
    int s  = blockIdx.x;           // chunk 0..31
    int og = blockIdx.y;           // 0..3
    int oc = threadIdx.x;          // 0..127
    __nv_bfloat16* gb = (__nv_bfloat16*)g_wA4;
    size_t blk = ((size_t)og * 32 + s) * 18432;     // elems (36864B/2)
#pragma unroll
    for (int t = 0; t < 3; t++) {
        size_t rh = blk + (size_t)(t * 2 + 0) * 3072 + oc * 24;
        size_t rl = blk + (size_t)(t * 2 + 1) * 3072 + oc * 24;
#pragma unroll
        for (int r = 0; r < 16; r++) {
            float w = cw[(size_t)(og * 128 + oc) * 1536 + (size_t)(s * 16 + r) * 3 + t];
            __nv_bfloat16 h = __float2bfloat16(w);
            gb[rh + r] = h;
            gb[rl + r] = __float2bfloat16(w - __bfloat162float(h));
        }
#pragma unroll
        for (int r = 16; r < 24; r++) { gb[rh + r] = __nv_bfloat16(0.f); gb[rl + r] = __nv_bfloat16(0.f); }
    }
}

// ---------------------------------------------------------------- A: v_word gather
__global__ void k_word(const int* __restrict__ words, const float* __restrict__ we) {
    int n = blockIdx.x;
    int w = words[n];
    float4 v = make_float4(0.f, 0.f, 0.f, 0.f);
    if (w != 0) v = ((const float4*)(we + (size_t)w * 512))[threadIdx.x];
    ((float4*)(g_u + (size_t)n * 1024))[threadIdx.x] = v;
}

// ---------------------------------------------------------------- B: HMMA conv
// CTA = 128 oc x 8 words, 512 thr (16 warps: wm(2) x wn(8)); warp = 64oc x 32pos.
// K: 32 chunks of 16 ic (chunk c == char position c). Taps via shifted B rows.
// SMEM buffer (x2): A 36864B: [tap3][spl2][oc128]x48B ; X 26112B: [w8*spl2][pos34]x48B
#define ABYTES 36864
#define XBYTES 26112
#define BUFB   (ABYTES + XBYTES)
#define CONV_SMEM (2 * BUFB + 1024)

__global__ __launch_bounds__(512, 1) void k_conv(
    const int* __restrict__ wic, const float* __restrict__ cb) {
    extern __shared__ char sm[];
    uint32_t sb = smem_u32(sm);
    int tid = threadIdx.x;
    int lane = tid & 31, w = tid >> 5;
    int wm = w >> 3, wn = w & 7;
    int nb0 = blockIdx.x * 8;
    int og  = blockIdx.y;
    int oc0 = og * 128;
    int* cs = (int*)(sm + 2 * BUFB);    // [8][32]

    if (tid < 256) cs[tid] = wic[(nb0 + (tid >> 5)) * 32 + (tid & 31)];
    // zero halo rows (pos rows 0 and 33) of both buffers
    for (int e = tid; e < 192; e += 512) {
        int buf = e >= 96, r = buf ? e - 96 : e;       // 96 = 16subs*2rows*3(16B)
        int sub = r / 6, rem = r % 6, row = (rem >= 3) ? 33 : 0, q = rem % 3;
        *(uint4*)(sm + buf * BUFB + ABYTES + sub * 1632 + row * 48 + q * 16) =
            make_uint4(0, 0, 0, 0);
    }
    __syncthreads();

    const char* gA = (const char*)g_wA4 + (size_t)og * 32 * ABYTES;

    // ---- copy issue for chunk s into buffer b
    auto issue = [&](int s, int b) {
        uint32_t Ab = sb + b * BUFB;
        const char* src = gA + (size_t)s * ABYTES;
        for (int i = tid; i < ABYTES / 16; i += 512)
            cp16(Ab + i * 16, src + i * 16);
        uint32_t Xb = Ab + ABYTES;
#pragma unroll
        for (int j = 0; j < 2; j++) {
            int e = tid + j * 512;             // 0..1023
            int ww = e >> 7, p = (e >> 6) & 1, l = (e >> 1) & 31, h = e & 1;
            int ch = cs[ww * 32 + s];
            const __nv_bfloat16* srcx = (p ? g_cel : g_ceh) + ch * 512 + l * 16 + h * 8;
            cp16(Xb + (ww * 2 + p) * 1632 + (l + 1) * 48 + h * 16, srcx);
        }
        cp_commit();
    };

    float acc[4][4][4];
#pragma unroll
    for (int i = 0; i < 4; i++)
#pragma unroll
        for (int j = 0; j < 4; j++)
#pragma unroll
            for (int q = 0; q < 4; q++) acc[i][j][q] = 0.f;

    // lane address components
    uint32_t aoff = (uint32_t)((wm * 64 + (lane & 15)) * 48 + (lane >> 4) * 16);
    uint32_t boff = (uint32_t)((lane & 7) * 48 + ((lane >> 3) & 1) * 16);

    issue(0, 0);
    for (int s = 0; s < 32; s++) {
        int b = s & 1;
        if (s < 31) { issue(s + 1, b ^ 1); cp_wait1(); } else cp_wait0();
        __syncthreads();

        uint32_t Ab = sb + b * BUFB;
        uint32_t Xb = Ab + ABYTES;
#pragma unroll
        for (int t = 0; t < 3; t++) {
            uint32_t ah[4][4], al[4][4];
#pragma unroll
            for (int mt = 0; mt < 4; mt++) {
                ldsm_x4(ah[mt], Ab + (t * 2 + 0) * 6144 + mt * 768 + aoff);
                ldsm_x4(al[mt], Ab + (t * 2 + 1) * 6144 + mt * 768 + aoff);
            }
            uint32_t bh[4][2], bl[4][2];
#pragma unroll
            for (int nt = 0; nt < 4; nt++) {
                uint32_t rb = (uint32_t)((nt * 8 + t) * 48);
                ldsm_x2(bh[nt], Xb + (wn * 2 + 0) * 1632 + rb + boff);
                ldsm_x2(bl[nt], Xb + (wn * 2 + 1) * 1632 + rb + boff);
            }
#pragma unroll
            for (int nt = 0; nt < 4; nt++)
#pragma unroll
                for (int mt = 0; mt < 4; mt++) {
                    mma16816(acc[mt][nt], ah[mt], bh[nt]);
                    mma16816(acc[mt][nt], al[mt], bh[nt]);
                    mma16816(acc[mt][nt], ah[mt], bl[nt]);
                }
        }
        __syncthreads();
    }

    // ---- epilogue: maxpool over 32 positions, add bias, store v_wch
    int n = nb0 + wn;
#pragma unroll
    for (int mt = 0; mt < 4; mt++) {
        float m0 = -3.4e38f, m1 = -3.4e38f;
#pragma unroll
        for (int nt = 0; nt < 4; nt++) {
            m0 = fmaxf(m0, fmaxf(acc[mt][nt][0], acc[mt][nt][1]));
            m1 = fmaxf(m1, fmaxf(acc[mt][nt][2], acc[mt][nt][3]));
        }
        m0 = fmaxf(m0, __shfl_xor_sync(0xffffffffu, m0, 1));
        m0 = fmaxf(m0, __shfl_xor_sync(0xffffffffu, m0, 2));
        m1 = fmaxf(m1, __shfl_xor_sync(0xffffffffu, m1, 1));
        m1 = fmaxf(m1, __shfl_xor_sync(0xffffffffu, m1, 2));
        if ((lane & 3) == 0) {
            int row = lane >> 2;
            int oc = oc0 + wm * 64 + mt * 16 + row;
            g_u[(size_t)n * 1024 + 512 + oc]     = m0 + cb[oc];
            g_u[(size_t)n * 1024 + 512 + oc + 8] = m1 + cb[oc + 8];
        }
    }
}

// ---------------------------------------------------------------- C1: repack sent W
__global__ void k_repack(const float* __restrict__ ws) {
    int i = blockIdx.x * 256 + threadIdx.x;
    g_wc[i] = ws[(size_t)i * 3 + 1];
}

// ---------------------------------------------------------------- C2: r = u@Wc^T + max
__global__ __launch_bounds__(256, 2) void k_sent(const float* __restrict__ csb) {
    __shared__ float Us[32 * 129];
    __shared__ float Wss[32 * 129];
    __shared__ float red[128 * 17];
    int t = threadIdx.x;
    int nb = blockIdx.x * 128;
    int o0 = blockIdx.y * 128;
    int tx = t & 15, ty = t >> 4;

    float acc[8][8];
#pragma unroll
    for (int i = 0; i < 8; i++)
#pragma unroll
        for (int j = 0; j < 8; j++) acc[i][j] = 0.f;

    for (int i0 = 0; i0 < 1024; i0 += 32) {
#pragma unroll
        for (int j = 0; j < 16; j++) {
            int i = t + j * 256;
            int n = i >> 5, k = i & 31;
            Us[k * 129 + n] = g_u[(size_t)(nb + n) * 1024 + i0 + k];
            Wss[k * 129 + n] = g_wc[(size_t)(o0 + n) * 1024 + i0 + k];
        }
        __syncthreads();
#pragma unroll 4
        for (int k = 0; k < 32; k++) {
            float xv[8], wv[8];
#pragma unroll
            for (int nn = 0; nn < 8; nn++) xv[nn] = Us[k * 129 + tx + nn * 16];
#pragma unroll
            for (int oo = 0; oo < 8; oo++) wv[oo] = Wss[k * 129 + ty * 8 + oo];
#pragma unroll
            for (int oo = 0; oo < 8; oo++)
#pragma unroll
                for (int nn = 0; nn < 8; nn++)
                    acc[oo][nn] = fmaf(wv[oo], xv[nn], acc[oo][nn]);
        }
        __syncthreads();
    }
#pragma unroll
    for (int oo = 0; oo < 8; oo++) {
        float m = acc[oo][0];
#pragma unroll
        for (int nn = 1; nn < 8; nn++) m = fmaxf(m, acc[oo][nn]);
        red[(ty * 8 + oo) * 17 + tx] = m;
    }
    __syncthreads();
    if (t < 128) {
        float m = red[t * 17];
#pragma unroll
        for (int j = 1; j < 16; j++) m = fmaxf(m, red[t * 17 + j]);
        g_pmax[blockIdx.x * 1024 + o0 + t] = m + csb[o0 + t];
    }
}

// ---------------------------------------------------------------- D2: lin1 + tanh
__global__ void k_lin1(const float* __restrict__ w1, const float* __restrict__ b1) {
    __shared__ float rm[1024];
    int t = threadIdx.x;   // 128
    for (int o = t; o < 1024; o += 128) {
        float m = g_pmax[o];
#pragma unroll
        for (int j = 1; j < 32; j++) m = fmaxf(m, g_pmax[j * 1024 + o]);
        rm[o] = m;
    }
    __syncthreads();
    int j = blockIdx.x * 128 + t;
    float s = b1[j];
    const float* wr = w1 + (size_t)j * 1024;
    for (int i = 0; i < 1024; i++) s = fmaf(rm[i], wr[i], s);
    g_h[j] = tanhf(s);
}

// ---------------------------------------------------------------- D3: lin2
__global__ void k_lin2(const float* __restrict__ w2, const float* __restrict__ b2,
                       float* __restrict__ out) {
    __shared__ float p0s[256], p1s[256];
    int t = threadIdx.x;
    float p0 = 0.f, p1 = 0.f;
    for (int i = t; i < 2048; i += 256) {
        float h = g_h[i];
        p0 = fmaf(h, w2[i], p0);
        p1 = fmaf(h, w2[2048 + i], p1);
    }
    p0s[t] = p0; p1s[t] = p1;
    __syncthreads();
    for (int s = 128; s > 0; s >>= 1) {
        if (t < s) { p0s[t] += p0s[t + s]; p1s[t] += p1s[t + s]; }
        __syncthreads();
    }
    if (t == 0) { out[0] = p0s[0] + b2[0]; out[1] = p1s[0] + b2[1]; }
}

// ----------------------------------------------------------------
extern "C" void kernel_launch(void* const* d_in, const int* in_sizes, int n_in,
                              void* d_out, int out_size) {
    const int*   words = (const int*)d_in[0];
    const int*   wic   = (const int*)d_in[1];
    const float* we    = (const float*)d_in[2];
    const float* ce    = (const float*)d_in[3];
    const float* cw    = (const float*)d_in[4];
    const float* cb    = (const float*)d_in[5];
    const float* ws    = (const float*)d_in[6];
    const float* csb   = (const float*)d_in[7];
    const float* w1    = (const float*)d_in[8];
    const float* b1    = (const float*)d_in[9];
    const float* w2    = (const float*)d_in[10];
    const float* b2    = (const float*)d_in[11];
    float* out = (float*)d_out;

    static int smem_set = 0;
    if (!smem_set) {
        cudaFuncSetAttribute(k_conv, cudaFuncAttributeMaxDynamicSharedMemorySize,
                             CONV_SMEM);
        smem_set = 1;
    }

    k_prep_ce<<<256, 256>>>(ce);
    k_prep_w <<<dim3(32, 4), 128>>>(cw);
    k_word   <<<4096, 128>>>(words, we);
    k_repack <<<4096, 256>>>(ws);
    k_conv   <<<dim3(512, 4), 512, CONV_SMEM>>>(wic, cb);
    k_sent   <<<dim3(32, 8), 256>>>(csb);
    k_lin1   <<<16, 128>>>(w1, b1);
    k_lin2   <<<1, 256>>>(w2, b2, out);
}

// round 6
// speedup vs baseline: 4.3701x; 1.3288x over previous
#include <cuda_runtime.h>
#include <cuda_fp16.h>
#include <stdint.h>
#include <math.h>

// ---------------------------------------------------------------- scratch
__device__ float g_u[4096 * 1024];      // [N][v_word(512) | v_wch(512)]
__device__ float g_wc[1024 * 1024];     // repacked conv_sent_w[:,:,1]
__device__ float g_pmax[32 * 1024];
__device__ float g_h[2048];
__device__ __half g_ceh[256 * 512];     // char emb transposed, fp16, x64 scale
// prepacked conv weights (fp16, x64 scale): [og(4)][chunk(32)] blocks of 36864B
//   block = [tap(3)][spl(2: hi,lo)][oc(128)] rows of 48B (16 fp16 + pad)
__device__ uint4 g_wA4[4 * 32 * 36864 / 16];

// ---------------------------------------------------------------- helpers
__device__ __forceinline__ uint32_t smem_u32(const void* p) {
    uint32_t a;
    asm("{ .reg .u64 t; cvta.to.shared.u64 t, %1; cvt.u32.u64 %0, t; }"
        : "=r"(a) : "l"(p));
    return a;
}
__device__ __forceinline__ void cp16(uint32_t dst, const void* src) {
    asm volatile("cp.async.cg.shared.global [%0], [%1], 16;"
                 :: "r"(dst), "l"(src) : "memory");
}
__device__ __forceinline__ void cp_commit() {
    asm volatile("cp.async.commit_group;" ::: "memory");
}
__device__ __forceinline__ void cp_wait0() {
    asm volatile("cp.async.wait_group 0;" ::: "memory");
}
__device__ __forceinline__ void cp_wait1() {
    asm volatile("cp.async.wait_group 1;" ::: "memory");
}
__device__ __forceinline__ void ldsm_x4(uint32_t* r, uint32_t addr) {
    asm volatile("ldmatrix.sync.aligned.m8n8.x4.shared.b16 {%0,%1,%2,%3}, [%4];"
                 : "=r"(r[0]), "=r"(r[1]), "=r"(r[2]), "=r"(r[3]) : "r"(addr));
}
__device__ __forceinline__ void ldsm_x2(uint32_t* r, uint32_t addr) {
    asm volatile("ldmatrix.sync.aligned.m8n8.x2.shared.b16 {%0,%1}, [%2];"
                 : "=r"(r[0]), "=r"(r[1]) : "r"(addr));
}
__device__ __forceinline__ void mma16816(float* c, const uint32_t* a, const uint32_t* b) {
    asm volatile(
        "mma.sync.aligned.m16n8k16.row.col.f32.f16.f16.f32 "
        "{%0,%1,%2,%3}, {%4,%5,%6,%7}, {%8,%9}, {%0,%1,%2,%3};"
        : "+f"(c[0]), "+f"(c[1]), "+f"(c[2]), "+f"(c[3])
        : "r"(a[0]), "r"(a[1]), "r"(a[2]), "r"(a[3]), "r"(b[0]), "r"(b[1]));
}

// ---------------------------------------------------------------- prepacks
// char emb -> transposed fp16 (x64): g_ceh[c][pos*16 + r] = ce[c][r*32+pos]*64
__global__ void k_prep_ce(const float* __restrict__ ce) {
    int c = blockIdx.x;
    for (int d = threadIdx.x; d < 512; d += 256) {
        float v = (c == 0) ? 0.f : ce[c * 512 + d] * 64.f;
        g_ceh[c * 512 + (d & 31) * 16 + (d >> 5)] = __float2half(v);
    }
}

// conv weights -> [og][chunk] blocks: [tap][hi/lo][oc128] rows of 24 fp16 (x64)
__global__ void k_prep_w(const float* __restrict__ cw) {
    int s  = blockIdx.x;           // chunk 0..31
    int og = blockIdx.y;           // 0..3
    int oc = threadIdx.x;          // 0..127
    __half* gb = (__half*)g_wA4;
    size_t blk = ((size_t)og * 32 + s) * 18432;     // elems (36864B/2)
#pragma unroll
    for (int t = 0; t < 3; t++) {
        size_t rh = blk + (size_t)(t * 2 + 0) * 3072 + oc * 24;
        size_t rl = blk + (size_t)(t * 2 + 1) * 3072 + oc * 24;
#pragma unroll
        for (int r = 0; r < 16; r++) {
            float w = cw[(size_t)(og * 128 + oc) * 1536 + (size_t)(s * 16 + r) * 3 + t] * 64.f;
            __half h = __float2half(w);
            gb[rh + r] = h;
            gb[rl + r] = __float2half(w - __half2float(h));
        }
#pragma unroll
        for (int r = 16; r < 24; r++) { gb[rh + r] = __half(0.f); gb[rl + r] = __half(0.f); }
    }
}

// ---------------------------------------------------------------- A: v_word gather
__global__ void k_word(const int* __restrict__ words, const float* __restrict__ we) {
    int n = blockIdx.x;
    int w = words[n];
    float4 v = make_float4(0.f, 0.f, 0.f, 0.f);
    if (w != 0) v = ((const float4*)(we + (size_t)w * 512))[threadIdx.x];
    ((float4*)(g_u + (size_t)n * 1024))[threadIdx.x] = v;
}

// ---------------------------------------------------------------- B: HMMA conv
// CTA = 128 oc x 8 words, 512 thr (16 warps: wm(2) x wn(8)); warp = 64oc x 32pos.
// K: 32 chunks of 16 ic (chunk c == char position c). Taps via shifted B rows.
// fp16 2-product split: acc = Whi*X + Wlo*X (both x64-scaled; epilogue /4096).
// SMEM buffer (x2): A 36864B: [tap3][spl2][oc128]x48B ; X 13056B: [w8][pos34]x48B
#define ABYTES 36864
#define XBYTES 13056
#define BUFB   (ABYTES + XBYTES)
#define CONV_SMEM (2 * BUFB + 1024)

__global__ __launch_bounds__(512, 1) void k_conv(
    const int* __restrict__ wic, const float* __restrict__ cb) {
    extern __shared__ char sm[];
    uint32_t sb = smem_u32(sm);
    int tid = threadIdx.x;
    int lane = tid & 31, w = tid >> 5;
    int wm = w >> 3, wn = w & 7;
    int nb0 = blockIdx.x * 8;
    int og  = blockIdx.y;
    int oc0 = og * 128;
    int* cs = (int*)(sm + 2 * BUFB);    // [8][32]

    if (tid < 256) cs[tid] = wic[(nb0 + (tid >> 5)) * 32 + (tid & 31)];
    // zero halo rows (pos rows 0 and 33) of both buffers: 8 subs x 2 rows x 3 q
    for (int e = tid; e < 96; e += 512) {
        int buf = e >= 48, r = buf ? e - 48 : e;
        int sub = r / 6, rem = r % 6, row = (rem >= 3) ? 33 : 0, q = rem % 3;
        *(uint4*)(sm + buf * BUFB + ABYTES + sub * 1632 + row * 48 + q * 16) =
            make_uint4(0, 0, 0, 0);
    }
    __syncthreads();

    const char* gA = (const char*)g_wA4 + (size_t)og * 32 * ABYTES;

    // ---- copy issue for chunk s into buffer b
    auto issue = [&](int s, int b) {
        uint32_t Ab = sb + b * BUFB;
        const char* src = gA + (size_t)s * ABYTES;
        for (int i = tid; i < ABYTES / 16; i += 512)
            cp16(Ab + i * 16, src + i * 16);
        uint32_t Xb = Ab + ABYTES;
        {
            int e = tid;                        // 0..511: ww(8) x l(32) x h(2)
            int ww = e >> 6, l = (e >> 1) & 31, h = e & 1;
            int ch = cs[ww * 32 + s];
            const __half* srcx = g_ceh + ch * 512 + l * 16 + h * 8;
            cp16(Xb + ww * 1632 + (l + 1) * 48 + h * 16, srcx);
        }
        cp_commit();
    };

    float acc[4][4][4];
#pragma unroll
    for (int i = 0; i < 4; i++)
#pragma unroll
        for (int j = 0; j < 4; j++)
#pragma unroll
            for (int q = 0; q < 4; q++) acc[i][j][q] = 0.f;

    // lane address components
    uint32_t aoff = (uint32_t)((wm * 64 + (lane & 15)) * 48 + (lane >> 4) * 16);
    uint32_t boff = (uint32_t)((lane & 7) * 48 + ((lane >> 3) & 1) * 16);

    issue(0, 0);
    for (int s = 0; s < 32; s++) {
        int b = s & 1;
        if (s < 31) { issue(s + 1, b ^ 1); cp_wait1(); } else cp_wait0();
        __syncthreads();

        uint32_t Ab = sb + b * BUFB;
        uint32_t Xb = Ab + ABYTES;
#pragma unroll
        for (int t = 0; t < 3; t++) {
            uint32_t ah[4][4], al[4][4];
#pragma unroll
            for (int mt = 0; mt < 4; mt++) {
                ldsm_x4(ah[mt], Ab + (t * 2 + 0) * 6144 + mt * 768 + aoff);
                ldsm_x4(al[mt], Ab + (t * 2 + 1) * 6144 + mt * 768 + aoff);
            }
            uint32_t bh[4][2];
#pragma unroll
            for (int nt = 0; nt < 4; nt++) {
                uint32_t rb = (uint32_t)((nt * 8 + t) * 48);
                ldsm_x2(bh[nt], Xb + wn * 1632 + rb + boff);
            }
#pragma unroll
            for (int nt = 0; nt < 4; nt++)
#pragma unroll
                for (int mt = 0; mt < 4; mt++) {
                    mma16816(acc[mt][nt], ah[mt], bh[nt]);
                    mma16816(acc[mt][nt], al[mt], bh[nt]);
                }
        }
        __syncthreads();
    }

    // ---- epilogue: maxpool over 32 positions, unscale, add bias, store v_wch
    int n = nb0 + wn;
#pragma unroll
    for (int mt = 0; mt < 4; mt++) {
        float m0 = -3.4e38f, m1 = -3.4e38f;
#pragma unroll
        for (int nt = 0; nt < 4; nt++) {
            m0 = fmaxf(m0, fmaxf(acc[mt][nt][0], acc[mt][nt][1]));
            m1 = fmaxf(m1, fmaxf(acc[mt][nt][2], acc[mt][nt][3]));
        }
        m0 = fmaxf(m0, __shfl_xor_sync(0xffffffffu, m0, 1));
        m0 = fmaxf(m0, __shfl_xor_sync(0xffffffffu, m0, 2));
        m1 = fmaxf(m1, __shfl_xor_sync(0xffffffffu, m1, 1));
        m1 = fmaxf(m1, __shfl_xor_sync(0xffffffffu, m1, 2));
        if ((lane & 3) == 0) {
            int row = lane >> 2;
            int oc = oc0 + wm * 64 + mt * 16 + row;
            g_u[(size_t)n * 1024 + 512 + oc]     = m0 * (1.f / 4096.f) + cb[oc];
            g_u[(size_t)n * 1024 + 512 + oc + 8] = m1 * (1.f / 4096.f) + cb[oc + 8];
        }
    }
}

// ---------------------------------------------------------------- C1: repack sent W
__global__ void k_repack(const float* __restrict__ ws) {
    int i = blockIdx.x * 256 + threadIdx.x;
    g_wc[i] = ws[(size_t)i * 3 + 1];
}

// ---------------------------------------------------------------- C2: r = u@Wc^T + max
__global__ __launch_bounds__(256, 2) void k_sent(const float* __restrict__ csb) {
    __shared__ float Us[32 * 129];
    __shared__ float Wss[32 * 129];
    __shared__ float red[128 * 17];
    int t = threadIdx.x;
    int nb = blockIdx.x * 128;
    int o0 = blockIdx.y * 128;
    int tx = t & 15, ty = t >> 4;

    float acc[8][8];
#pragma unroll
    for (int i = 0; i < 8; i++)
#pragma unroll
        for (int j = 0; j < 8; j++) acc[i][j] = 0.f;

    for (int i0 = 0; i0 < 1024; i0 += 32) {
#pragma unroll
        for (int j = 0; j < 16; j++) {
            int i = t + j * 256;
            int n = i >> 5, k = i & 31;
            Us[k * 129 + n] = g_u[(size_t)(nb + n) * 1024 + i0 + k];
            Wss[k * 129 + n] = g_wc[(size_t)(o0 + n) * 1024 + i0 + k];
        }
        __syncthreads();
#pragma unroll 4
        for (int k = 0; k < 32; k++) {
            float xv[8], wv[8];
#pragma unroll
            for (int nn = 0; nn < 8; nn++) xv[nn] = Us[k * 129 + tx + nn * 16];
#pragma unroll
            for (int oo = 0; oo < 8; oo++) wv[oo] = Wss[k * 129 + ty * 8 + oo];
#pragma unroll
            for (int oo = 0; oo < 8; oo++)
#pragma unroll
                for (int nn = 0; nn < 8; nn++)
                    acc[oo][nn] = fmaf(wv[oo], xv[nn], acc[oo][nn]);
        }
        __syncthreads();
    }
#pragma unroll
    for (int oo = 0; oo < 8; oo++) {
        float m = acc[oo][0];
#pragma unroll
        for (int nn = 1; nn < 8; nn++) m = fmaxf(m, acc[oo][nn]);
        red[(ty * 8 + oo) * 17 + tx] = m;
    }
    __syncthreads();
    if (t < 128) {
        float m = red[t * 17];
#pragma unroll
        for (int j = 1; j < 16; j++) m = fmaxf(m, red[t * 17 + j]);
        g_pmax[blockIdx.x * 1024 + o0 + t] = m + csb[o0 + t];
    }
}

// ---------------------------------------------------------------- D2: lin1 + tanh
__global__ void k_lin1(const float* __restrict__ w1, const float* __restrict__ b1) {
    __shared__ float rm[1024];
    int t = threadIdx.x;   // 128
    for (int o = t; o < 1024; o += 128) {
        float m = g_pmax[o];
#pragma unroll
        for (int j = 1; j < 32; j++) m = fmaxf(m, g_pmax[j * 1024 + o]);
        rm[o] = m;
    }
    __syncthreads();
    int j = blockIdx.x * 128 + t;
    float s = b1[j];
    const float* wr = w1 + (size_t)j * 1024;
    for (int i = 0; i < 1024; i++) s = fmaf(rm[i], wr[i], s);
    g_h[j] = tanhf(s);
}

// ---------------------------------------------------------------- D3: lin2
__global__ void k_lin2(const float* __restrict__ w2, const float* __restrict__ b2,
                       float* __restrict__ out) {
    __shared__ float p0s[256], p1s[256];
    int t = threadIdx.x;
    float p0 = 0.f, p1 = 0.f;
    for (int i = t; i < 2048; i += 256) {
        float h = g_h[i];
        p0 = fmaf(h, w2[i], p0);
        p1 = fmaf(h, w2[2048 + i], p1);
    }
    p0s[t] = p0; p1s[t] = p1;
    __syncthreads();
    for (int s = 128; s > 0; s >>= 1) {
        if (t < s) { p0s[t] += p0s[t + s]; p1s[t] += p1s[t + s]; }
        __syncthreads();
    }
    if (t == 0) { out[0] = p0s[0] + b2[0]; out[1] = p1s[0] + b2[1]; }
}

// ----------------------------------------------------------------
extern "C" void kernel_launch(void* const* d_in, const int* in_sizes, int n_in,
                              void* d_out, int out_size) {
    const int*   words = (const int*)d_in[0];
    const int*   wic   = (const int*)d_in[1];
    const float* we    = (const float*)d_in[2];
    const float* ce    = (const float*)d_in[3];
    const float* cw    = (const float*)d_in[4];
    const float* cb    = (const float*)d_in[5];
    const float* ws    = (const float*)d_in[6];
    const float* csb   = (const float*)d_in[7];
    const float* w1    = (const float*)d_in[8];
    const float* b1    = (const float*)d_in[9];
    const float* w2    = (const float*)d_in[10];
    const float* b2    = (const float*)d_in[11];
    float* out = (float*)d_out;

    static int smem_set = 0;
    if (!smem_set) {
        cudaFuncSetAttribute(k_conv, cudaFuncAttributeMaxDynamicSharedMemorySize,
                             CONV_SMEM);
        smem_set = 1;
    }

    k_prep_ce<<<256, 256>>>(ce);
    k_prep_w <<<dim3(32, 4), 128>>>(cw);
    k_word   <<<4096, 128>>>(words, we);
    k_repack <<<4096, 256>>>(ws);
    k_conv   <<<dim3(512, 4), 512, CONV_SMEM>>>(wic, cb);
    k_sent   <<<dim3(32, 8), 256>>>(csb);
    k_lin1   <<<16, 128>>>(w1, b1);
    k_lin2   <<<1, 256>>>(w2, b2, out);
}

// round 7
// speedup vs baseline: 6.1907x; 1.4166x over previous
#include <cuda_runtime.h>
#include <cuda_fp16.h>
#include <stdint.h>
#include <math.h>

// ---------------------------------------------------------------- scratch
__device__ float g_u[4096 * 1024];      // [N][v_word(512) | v_wch(512)]
__device__ float g_wc[1024 * 1024];     // repacked conv_sent_w[:,:,1]
__device__ float g_pmax[32 * 1024];
__device__ float g_h[2048];
__device__ __half g_ceh[256 * 512];     // char emb transposed, fp16, x64 scale
// prepacked conv weights (fp16, x64): [og(4)][chunk(32)] blocks of 18432B
//   block = [tap(3)][oc(128)] rows of 48B (16 fp16 + pad)
__device__ uint4 g_wA4[4 * 32 * 18432 / 16];

// ---------------------------------------------------------------- helpers
__device__ __forceinline__ uint32_t smem_u32(const void* p) {
    uint32_t a;
    asm("{ .reg .u64 t; cvta.to.shared.u64 t, %1; cvt.u32.u64 %0, t; }"
        : "=r"(a) : "l"(p));
    return a;
}
__device__ __forceinline__ void cp16(uint32_t dst, const void* src) {
    asm volatile("cp.async.cg.shared.global [%0], [%1], 16;"
                 :: "r"(dst), "l"(src) : "memory");
}
__device__ __forceinline__ void cp_commit() {
    asm volatile("cp.async.commit_group;" ::: "memory");
}
__device__ __forceinline__ void cp_wait0() {
    asm volatile("cp.async.wait_group 0;" ::: "memory");
}
__device__ __forceinline__ void cp_wait1() {
    asm volatile("cp.async.wait_group 1;" ::: "memory");
}
__device__ __forceinline__ void ldsm_x4(uint32_t* r, uint32_t addr) {
    asm volatile("ldmatrix.sync.aligned.m8n8.x4.shared.b16 {%0,%1,%2,%3}, [%4];"
                 : "=r"(r[0]), "=r"(r[1]), "=r"(r[2]), "=r"(r[3]) : "r"(addr));
}
__device__ __forceinline__ void ldsm_x2(uint32_t* r, uint32_t addr) {
    asm volatile("ldmatrix.sync.aligned.m8n8.x2.shared.b16 {%0,%1}, [%2];"
                 : "=r"(r[0]), "=r"(r[1]) : "r"(addr));
}
__device__ __forceinline__ void mma16816(float* c, const uint32_t* a, const uint32_t* b) {
    asm volatile(
        "mma.sync.aligned.m16n8k16.row.col.f32.f16.f16.f32 "
        "{%0,%1,%2,%3}, {%4,%5,%6,%7}, {%8,%9}, {%0,%1,%2,%3};"
        : "+f"(c[0]), "+f"(c[1]), "+f"(c[2]), "+f"(c[3])
        : "r"(a[0]), "r"(a[1]), "r"(a[2]), "r"(a[3]), "r"(b[0]), "r"(b[1]));
}

// ---------------------------------------------------------------- prepacks
// char emb -> transposed fp16 (x64): g_ceh[c][pos*16 + r] = ce[c][r*32+pos]*64
__global__ void k_prep_ce(const float* __restrict__ ce) {
    int c = blockIdx.x;
    for (int d = threadIdx.x; d < 512; d += 256) {
        float v = (c == 0) ? 0.f : ce[c * 512 + d] * 64.f;
        g_ceh[c * 512 + (d & 31) * 16 + (d >> 5)] = __float2half(v);
    }
}

// conv weights -> [og][chunk] blocks: [tap][oc128] rows of 24 fp16 (x64)
__global__ void k_prep_w(const float* __restrict__ cw) {
    int s  = blockIdx.x;           // chunk 0..31
    int og = blockIdx.y;           // 0..3
    int oc = threadIdx.x;          // 0..127
    __half* gb = (__half*)g_wA4;
    size_t blk = ((size_t)og * 32 + s) * 9216;     // elems (18432B/2)
#pragma unroll
    for (int t = 0; t < 3; t++) {
        size_t rh = blk + (size_t)t * 3072 + oc * 24;
#pragma unroll
        for (int r = 0; r < 16; r++) {
            float w = cw[(size_t)(og * 128 + oc) * 1536 + (size_t)(s * 16 + r) * 3 + t] * 64.f;
            gb[rh + r] = __float2half(w);
        }
#pragma unroll
        for (int r = 16; r < 24; r++) gb[rh + r] = __half(0.f);
    }
}

// ---------------------------------------------------------------- A: v_word gather
__global__ void k_word(const int* __restrict__ words, const float* __restrict__ we) {
    int n = blockIdx.x;
    int w = words[n];
    float4 v = make_float4(0.f, 0.f, 0.f, 0.f);
    if (w != 0) v = ((const float4*)(we + (size_t)w * 512))[threadIdx.x];
    ((float4*)(g_u + (size_t)n * 1024))[threadIdx.x] = v;
}

// ---------------------------------------------------------------- B: HMMA conv
// CTA = 128 oc x 8 words, 512 thr (16 warps: wm(2) x wn(8)); warp = 64oc x 32pos.
// K: 32 chunks of 16 ic. Taps via shifted B rows. Single fp16 product (x4096,
// epilogue /4096).
// SMEM buffer (x2): A 18432B: [tap3][oc128]x48B ; X 13056B: [w8][pos34]x48B
#define ABYTES 18432
#define XBYTES 13056
#define BUFB   (ABYTES + XBYTES)
#define CONV_SMEM (2 * BUFB + 1024)

__global__ __launch_bounds__(512, 1) void k_conv(
    const int* __restrict__ wic, const float* __restrict__ cb) {
    extern __shared__ char sm[];
    uint32_t sb = smem_u32(sm);
    int tid = threadIdx.x;
    int lane = tid & 31, w = tid >> 5;
    int wm = w >> 3, wn = w & 7;
    int nb0 = blockIdx.x * 8;
    int og  = blockIdx.y;
    int oc0 = og * 128;
    int* cs = (int*)(sm + 2 * BUFB);    // [8][32]

    if (tid < 256) cs[tid] = wic[(nb0 + (tid >> 5)) * 32 + (tid & 31)];
    // zero halo rows (pos rows 0 and 33) of both buffers: 8 subs x 2 rows x 3 q
    for (int e = tid; e < 96; e += 512) {
        int buf = e >= 48, r = buf ? e - 48 : e;
        int sub = r / 6, rem = r % 6, row = (rem >= 3) ? 33 : 0, q = rem % 3;
        *(uint4*)(sm + buf * BUFB + ABYTES + sub * 1632 + row * 48 + q * 16) =
            make_uint4(0, 0, 0, 0);
    }
    __syncthreads();

    const char* gA = (const char*)g_wA4 + (size_t)og * 32 * ABYTES;

    // ---- copy issue for chunk s into buffer b
    auto issue = [&](int s, int b) {
        uint32_t Ab = sb + b * BUFB;
        const char* src = gA + (size_t)s * ABYTES;
        for (int i = tid; i < ABYTES / 16; i += 512)
            cp16(Ab + i * 16, src + i * 16);
        uint32_t Xb = Ab + ABYTES;
        {
            int e = tid;                        // 0..511: ww(8) x l(32) x h(2)
            int ww = e >> 6, l = (e >> 1) & 31, h = e & 1;
            int ch = cs[ww * 32 + s];
            const __half* srcx = g_ceh + ch * 512 + l * 16 + h * 8;
            cp16(Xb + ww * 1632 + (l + 1) * 48 + h * 16, srcx);
        }
        cp_commit();
    };

    float acc[4][4][4];
#pragma unroll
    for (int i = 0; i < 4; i++)
#pragma unroll
        for (int j = 0; j < 4; j++)
#pragma unroll
            for (int q = 0; q < 4; q++) acc[i][j][q] = 0.f;

    // lane address components
    uint32_t aoff = (uint32_t)((wm * 64 + (lane & 15)) * 48 + (lane >> 4) * 16);
    uint32_t boff = (uint32_t)((lane & 7) * 48 + ((lane >> 3) & 1) * 16);

    issue(0, 0);
    for (int s = 0; s < 32; s++) {
        int b = s & 1;
        if (s < 31) { issue(s + 1, b ^ 1); cp_wait1(); } else cp_wait0();
        __syncthreads();

        uint32_t Ab = sb + b * BUFB;
        uint32_t Xb = Ab + ABYTES;
#pragma unroll
        for (int t = 0; t < 3; t++) {
            uint32_t ah[4][4];
#pragma unroll
            for (int mt = 0; mt < 4; mt++)
                ldsm_x4(ah[mt], Ab + t * 6144 + mt * 768 + aoff);
            uint32_t bh[4][2];
#pragma unroll
            for (int nt = 0; nt < 4; nt++) {
                uint32_t rb = (uint32_t)((nt * 8 + t) * 48);
                ldsm_x2(bh[nt], Xb + wn * 1632 + rb + boff);
            }
#pragma unroll
            for (int nt = 0; nt < 4; nt++)
#pragma unroll
                for (int mt = 0; mt < 4; mt++)
                    mma16816(acc[mt][nt], ah[mt], bh[nt]);
        }
        __syncthreads();
    }

    // ---- epilogue: maxpool over 32 positions, unscale, add bias, store v_wch
    int n = nb0 + wn;
#pragma unroll
    for (int mt = 0; mt < 4; mt++) {
        float m0 = -3.4e38f, m1 = -3.4e38f;
#pragma unroll
        for (int nt = 0; nt < 4; nt++) {
            m0 = fmaxf(m0, fmaxf(acc[mt][nt][0], acc[mt][nt][1]));
            m1 = fmaxf(m1, fmaxf(acc[mt][nt][2], acc[mt][nt][3]));
        }
        m0 = fmaxf(m0, __shfl_xor_sync(0xffffffffu, m0, 1));
        m0 = fmaxf(m0, __shfl_xor_sync(0xffffffffu, m0, 2));
        m1 = fmaxf(m1, __shfl_xor_sync(0xffffffffu, m1, 1));
        m1 = fmaxf(m1, __shfl_xor_sync(0xffffffffu, m1, 2));
        if ((lane & 3) == 0) {
            int row = lane >> 2;
            int oc = oc0 + wm * 64 + mt * 16 + row;
            g_u[(size_t)n * 1024 + 512 + oc]     = m0 * (1.f / 4096.f) + cb[oc];
            g_u[(size_t)n * 1024 + 512 + oc + 8] = m1 * (1.f / 4096.f) + cb[oc + 8];
        }
    }
}

// ---------------------------------------------------------------- C1: repack sent W
__global__ void k_repack(const float* __restrict__ ws) {
    int i = blockIdx.x * 256 + threadIdx.x;
    g_wc[i] = ws[(size_t)i * 3 + 1];
}

// ---------------------------------------------------------------- C2: r = u@Wc^T + max
__global__ __launch_bounds__(256, 2) void k_sent(const float* __restrict__ csb) {
    __shared__ float Us[32 * 129];
    __shared__ float Wss[32 * 129];
    __shared__ float red[128 * 17];
    int t = threadIdx.x;
    int nb = blockIdx.x * 128;
    int o0 = blockIdx.y * 128;
    int tx = t & 15, ty = t >> 4;

    float acc[8][8];
#pragma unroll
    for (int i = 0; i < 8; i++)
#pragma unroll
        for (int j = 0; j < 8; j++) acc[i][j] = 0.f;

    for (int i0 = 0; i0 < 1024; i0 += 32) {
#pragma unroll
        for (int j = 0; j < 16; j++) {
            int i = t + j * 256;
            int n = i >> 5, k = i & 31;
            Us[k * 129 + n] = g_u[(size_t)(nb + n) * 1024 + i0 + k];
            Wss[k * 129 + n] = g_wc[(size_t)(o0 + n) * 1024 + i0 + k];
        }
        __syncthreads();
#pragma unroll 4
        for (int k = 0; k < 32; k++) {
            float xv[8], wv[8];
#pragma unroll
            for (int nn = 0; nn < 8; nn++) xv[nn] = Us[k * 129 + tx + nn * 16];
#pragma unroll
            for (int oo = 0; oo < 8; oo++) wv[oo] = Wss[k * 129 + ty * 8 + oo];
#pragma unroll
            for (int oo = 0; oo < 8; oo++)
#pragma unroll
                for (int nn = 0; nn < 8; nn++)
                    acc[oo][nn] = fmaf(wv[oo], xv[nn], acc[oo][nn]);
        }
        __syncthreads();
    }
#pragma unroll
    for (int oo = 0; oo < 8; oo++) {
        float m = acc[oo][0];
#pragma unroll
        for (int nn = 1; nn < 8; nn++) m = fmaxf(m, acc[oo][nn]);
        red[(ty * 8 + oo) * 17 + tx] = m;
    }
    __syncthreads();
    if (t < 128) {
        float m = red[t * 17];
#pragma unroll
        for (int j = 1; j < 16; j++) m = fmaxf(m, red[t * 17 + j]);
        g_pmax[blockIdx.x * 1024 + o0 + t] = m + csb[o0 + t];
    }
}

// ---------------------------------------------------------------- D2: lin1 + tanh
__global__ void k_lin1(const float* __restrict__ w1, const float* __restrict__ b1) {
    __shared__ float rm[1024];
    int t = threadIdx.x;   // 128
    for (int o = t; o < 1024; o += 128) {
        float m = g_pmax[o];
#pragma unroll
        for (int j = 1; j < 32; j++) m = fmaxf(m, g_pmax[j * 1024 + o]);
        rm[o] = m;
    }
    __syncthreads();
    int j = blockIdx.x * 128 + t;
    float s = b1[j];
    const float* wr = w1 + (size_t)j * 1024;
    for (int i = 0; i < 1024; i++) s = fmaf(rm[i], wr[i], s);
    g_h[j] = tanhf(s);
}

// ---------------------------------------------------------------- D3: lin2
__global__ void k_lin2(const float* __restrict__ w2, const float* __restrict__ b2,
                       float* __restrict__ out) {
    __shared__ float p0s[256], p1s[256];
    int t = threadIdx.x;
    float p0 = 0.f, p1 = 0.f;
    for (int i = t; i < 2048; i += 256) {
        float h = g_h[i];
        p0 = fmaf(h, w2[i], p0);
        p1 = fmaf(h, w2[2048 + i], p1);
    }
    p0s[t] = p0; p1s[t] = p1;
    __syncthreads();
    for (int s = 128; s > 0; s >>= 1) {
        if (t < s) { p0s[t] += p0s[t + s]; p1s[t] += p1s[t + s]; }
        __syncthreads();
    }
    if (t == 0) { out[0] = p0s[0] + b2[0]; out[1] = p1s[0] + b2[1]; }
}

// ----------------------------------------------------------------
extern "C" void kernel_launch(void* const* d_in, const int* in_sizes, int n_in,
                              void* d_out, int out_size) {
    const int*   words = (const int*)d_in[0];
    const int*   wic   = (const int*)d_in[1];
    const float* we    = (const float*)d_in[2];
    const float* ce    = (const float*)d_in[3];
    const float* cw    = (const float*)d_in[4];
    const float* cb    = (const float*)d_in[5];
    const float* ws    = (const float*)d_in[6];
    const float* csb   = (const float*)d_in[7];
    const float* w1    = (const float*)d_in[8];
    const float* b1    = (const float*)d_in[9];
    const float* w2    = (const float*)d_in[10];
    const float* b2    = (const float*)d_in[11];
    float* out = (float*)d_out;

    static int smem_set = 0;
    if (!smem_set) {
        cudaFuncSetAttribute(k_conv, cudaFuncAttributeMaxDynamicSharedMemorySize,
                             CONV_SMEM);
        smem_set = 1;
    }

    k_prep_ce<<<256, 256>>>(ce);
    k_prep_w <<<dim3(32, 4), 128>>>(cw);
    k_word   <<<4096, 128>>>(words, we);
    k_repack <<<4096, 256>>>(ws);
    k_conv   <<<dim3(512, 4), 512, CONV_SMEM>>>(wic, cb);
    k_sent   <<<dim3(32, 8), 256>>>(csb);
    k_lin1   <<<16, 128>>>(w1, b1);
    k_lin2   <<<1, 256>>>(w2, b2, out);
}

// round 8
// speedup vs baseline: 8.6544x; 1.3980x over previous
#include <cuda_runtime.h>
#include <cuda_fp16.h>
#include <stdint.h>
#include <math.h>

// ---------------------------------------------------------------- scratch
__device__ __half g_uh[4096 * 1024];    // [N][v_word(512) | v_wch(512)] fp16
__device__ __half g_wch[1024 * 1024];   // repacked conv_sent_w[:,:,1] fp16
__device__ float g_pmax[32 * 1024];
__device__ float g_rm[1024];
__device__ float g_h[2048];
__device__ __half g_ceh[256 * 512];     // char emb transposed, fp16, x64 scale
// prepacked conv weights (fp16, x64): [og(4)][chunk(32)] blocks of 18432B
__device__ uint4 g_wA4[4 * 32 * 18432 / 16];

// ---------------------------------------------------------------- helpers
__device__ __forceinline__ uint32_t smem_u32(const void* p) {
    uint32_t a;
    asm("{ .reg .u64 t; cvta.to.shared.u64 t, %1; cvt.u32.u64 %0, t; }"
        : "=r"(a) : "l"(p));
    return a;
}
__device__ __forceinline__ void cp16(uint32_t dst, const void* src) {
    asm volatile("cp.async.cg.shared.global [%0], [%1], 16;"
                 :: "r"(dst), "l"(src) : "memory");
}
__device__ __forceinline__ void cp_commit() {
    asm volatile("cp.async.commit_group;" ::: "memory");
}
__device__ __forceinline__ void cp_wait0() {
    asm volatile("cp.async.wait_group 0;" ::: "memory");
}
__device__ __forceinline__ void cp_wait1() {
    asm volatile("cp.async.wait_group 1;" ::: "memory");
}
__device__ __forceinline__ void ldsm_x4(uint32_t* r, uint32_t addr) {
    asm volatile("ldmatrix.sync.aligned.m8n8.x4.shared.b16 {%0,%1,%2,%3}, [%4];"
                 : "=r"(r[0]), "=r"(r[1]), "=r"(r[2]), "=r"(r[3]) : "r"(addr));
}
__device__ __forceinline__ void ldsm_x2(uint32_t* r, uint32_t addr) {
    asm volatile("ldmatrix.sync.aligned.m8n8.x2.shared.b16 {%0,%1}, [%2];"
                 : "=r"(r[0]), "=r"(r[1]) : "r"(addr));
}
__device__ __forceinline__ void mma16816(float* c, const uint32_t* a, const uint32_t* b) {
    asm volatile(
        "mma.sync.aligned.m16n8k16.row.col.f32.f16.f16.f32 "
        "{%0,%1,%2,%3}, {%4,%5,%6,%7}, {%8,%9}, {%0,%1,%2,%3};"
        : "+f"(c[0]), "+f"(c[1]), "+f"(c[2]), "+f"(c[3])
        : "r"(a[0]), "r"(a[1]), "r"(a[2]), "r"(a[3]), "r"(b[0]), "r"(b[1]));
}

// ---------------------------------------------------------------- prepacks
__global__ void k_prep_ce(const float* __restrict__ ce) {
    int c = blockIdx.x;
    for (int d = threadIdx.x; d < 512; d += 256) {
        float v = (c == 0) ? 0.f : ce[c * 512 + d] * 64.f;
        g_ceh[c * 512 + (d & 31) * 16 + (d >> 5)] = __float2half(v);
    }
}

__global__ void k_prep_w(const float* __restrict__ cw) {
    int s  = blockIdx.x;
    int og = blockIdx.y;
    int oc = threadIdx.x;
    __half* gb = (__half*)g_wA4;
    size_t blk = ((size_t)og * 32 + s) * 9216;
#pragma unroll
    for (int t = 0; t < 3; t++) {
        size_t rh = blk + (size_t)t * 3072 + oc * 24;
#pragma unroll
        for (int r = 0; r < 16; r++) {
            float w = cw[(size_t)(og * 128 + oc) * 1536 + (size_t)(s * 16 + r) * 3 + t] * 64.f;
            gb[rh + r] = __float2half(w);
        }
#pragma unroll
        for (int r = 16; r < 24; r++) gb[rh + r] = __half(0.f);
    }
}

// ---------------------------------------------------------------- A: v_word gather (fp16 out)
__global__ void k_word(const int* __restrict__ words, const float* __restrict__ we) {
    int n = blockIdx.x;
    int w = words[n];
    float4 v = make_float4(0.f, 0.f, 0.f, 0.f);
    if (w != 0) v = ((const float4*)(we + (size_t)w * 512))[threadIdx.x];
    __half2* dst = (__half2*)(g_uh + (size_t)n * 1024) + threadIdx.x * 2;
    dst[0] = __floats2half2_rn(v.x, v.y);
    dst[1] = __floats2half2_rn(v.z, v.w);
}

// ---------------------------------------------------------------- B: HMMA conv
#define ABYTES 18432
#define XBYTES 13056
#define BUFB   (ABYTES + XBYTES)
#define CONV_SMEM (2 * BUFB + 1024)

__global__ __launch_bounds__(512, 1) void k_conv(
    const int* __restrict__ wic, const float* __restrict__ cb) {
    extern __shared__ char sm[];
    uint32_t sb = smem_u32(sm);
    int tid = threadIdx.x;
    int lane = tid & 31, w = tid >> 5;
    int wm = w >> 3, wn = w & 7;
    int nb0 = blockIdx.x * 8;
    int og  = blockIdx.y;
    int oc0 = og * 128;
    int* cs = (int*)(sm + 2 * BUFB);

    if (tid < 256) cs[tid] = wic[(nb0 + (tid >> 5)) * 32 + (tid & 31)];
    for (int e = tid; e < 96; e += 512) {
        int buf = e >= 48, r = buf ? e - 48 : e;
        int sub = r / 6, rem = r % 6, row = (rem >= 3) ? 33 : 0, q = rem % 3;
        *(uint4*)(sm + buf * BUFB + ABYTES + sub * 1632 + row * 48 + q * 16) =
            make_uint4(0, 0, 0, 0);
    }
    __syncthreads();

    const char* gA = (const char*)g_wA4 + (size_t)og * 32 * ABYTES;

    auto issue = [&](int s, int b) {
        uint32_t Ab = sb + b * BUFB;
        const char* src = gA + (size_t)s * ABYTES;
        for (int i = tid; i < ABYTES / 16; i += 512)
            cp16(Ab + i * 16, src + i * 16);
        uint32_t Xb = Ab + ABYTES;
        {
            int e = tid;
            int ww = e >> 6, l = (e >> 1) & 31, h = e & 1;
            int ch = cs[ww * 32 + s];
            const __half* srcx = g_ceh + ch * 512 + l * 16 + h * 8;
            cp16(Xb + ww * 1632 + (l + 1) * 48 + h * 16, srcx);
        }
        cp_commit();
    };

    float acc[4][4][4];
#pragma unroll
    for (int i = 0; i < 4; i++)
#pragma unroll
        for (int j = 0; j < 4; j++)
#pragma unroll
            for (int q = 0; q < 4; q++) acc[i][j][q] = 0.f;

    uint32_t aoff = (uint32_t)((wm * 64 + (lane & 15)) * 48 + (lane >> 4) * 16);
    uint32_t boff = (uint32_t)((lane & 7) * 48 + ((lane >> 3) & 1) * 16);

    issue(0, 0);
    for (int s = 0; s < 32; s++) {
        int b = s & 1;
        if (s < 31) { issue(s + 1, b ^ 1); cp_wait1(); } else cp_wait0();
        __syncthreads();

        uint32_t Ab = sb + b * BUFB;
        uint32_t Xb = Ab + ABYTES;
#pragma unroll
        for (int t = 0; t < 3; t++) {
            uint32_t ah[4][4];
#pragma unroll
            for (int mt = 0; mt < 4; mt++)
                ldsm_x4(ah[mt], Ab + t * 6144 + mt * 768 + aoff);
            uint32_t bh[4][2];
#pragma unroll
            for (int nt = 0; nt < 4; nt++) {
                uint32_t rb = (uint32_t)((nt * 8 + t) * 48);
                ldsm_x2(bh[nt], Xb + wn * 1632 + rb + boff);
            }
#pragma unroll
            for (int nt = 0; nt < 4; nt++)
#pragma unroll
                for (int mt = 0; mt < 4; mt++)
                    mma16816(acc[mt][nt], ah[mt], bh[nt]);
        }
        __syncthreads();
    }

    int n = nb0 + wn;
#pragma unroll
    for (int mt = 0; mt < 4; mt++) {
        float m0 = -3.4e38f, m1 = -3.4e38f;
#pragma unroll
        for (int nt = 0; nt < 4; nt++) {
            m0 = fmaxf(m0, fmaxf(acc[mt][nt][0], acc[mt][nt][1]));
            m1 = fmaxf(m1, fmaxf(acc[mt][nt][2], acc[mt][nt][3]));
        }
        m0 = fmaxf(m0, __shfl_xor_sync(0xffffffffu, m0, 1));
        m0 = fmaxf(m0, __shfl_xor_sync(0xffffffffu, m0, 2));
        m1 = fmaxf(m1, __shfl_xor_sync(0xffffffffu, m1, 1));
        m1 = fmaxf(m1, __shfl_xor_sync(0xffffffffu, m1, 2));
        if ((lane & 3) == 0) {
            int row = lane >> 2;
            int oc = oc0 + wm * 64 + mt * 16 + row;
            g_uh[(size_t)n * 1024 + 512 + oc]     = __float2half(m0 * (1.f / 4096.f) + cb[oc]);
            g_uh[(size_t)n * 1024 + 512 + oc + 8] = __float2half(m1 * (1.f / 4096.f) + cb[oc + 8]);
        }
    }
}

// ---------------------------------------------------------------- C1: repack sent W (fp16)
__global__ void k_repack(const float* __restrict__ ws) {
    int i = blockIdx.x * 256 + threadIdx.x;
    g_wch[i] = __float2half(ws[(size_t)i * 3 + 1]);
}

// ---------------------------------------------------------------- C2: HMMA r = u@Wc^T + colmax
// CTA 256 thr (8 warps: wm2 x wn4), tile 128o x 128n, K=1024 in 32 chunks of 32.
// Tiles [row][32 fp16] pitch 80B, double buffered.
__global__ __launch_bounds__(256, 2) void k_sent(const float* __restrict__ csb) {
    __shared__ __align__(16) char smem[2 * 20480];
    __shared__ float red[128 * 5];
    uint32_t sb = smem_u32(smem);
    int tid = threadIdx.x;
    int lane = tid & 31, w = tid >> 5;
    int wm = w >> 2, wn = w & 3;
    int nb = blockIdx.x * 128;
    int o0 = blockIdx.y * 128;

    auto issue = [&](int kc, int b) {
        uint32_t Ub = sb + b * 20480;
#pragma unroll
        for (int it = 0; it < 2; it++) {
            int e = tid + it * 256;            // 0..511
            int r = e >> 2, q = e & 3;
            cp16(Ub + r * 80 + q * 16, g_uh + (size_t)(nb + r) * 1024 + kc * 32 + q * 8);
        }
        uint32_t Wb = Ub + 10240;
#pragma unroll
        for (int it = 0; it < 2; it++) {
            int e = tid + it * 256;
            int r = e >> 2, q = e & 3;
            cp16(Wb + r * 80 + q * 16, g_wch + (size_t)(o0 + r) * 1024 + kc * 32 + q * 8);
        }
        cp_commit();
    };

    float acc[4][4][4];
#pragma unroll
    for (int i = 0; i < 4; i++)
#pragma unroll
        for (int j = 0; j < 4; j++)
#pragma unroll
            for (int q = 0; q < 4; q++) acc[i][j][q] = 0.f;

    uint32_t aoff = (uint32_t)((wm * 64 + (lane & 15)) * 80 + (lane >> 4) * 16);
    uint32_t boff = (uint32_t)((wn * 32 + (lane & 7)) * 80 + ((lane >> 3) & 1) * 16);

    issue(0, 0);
    for (int kc = 0; kc < 32; kc++) {
        int b = kc & 1;
        if (kc < 31) { issue(kc + 1, b ^ 1); cp_wait1(); } else cp_wait0();
        __syncthreads();
        uint32_t Ub = sb + b * 20480;
        uint32_t Wb = Ub + 10240;
#pragma unroll
        for (int ks = 0; ks < 2; ks++) {
            uint32_t a[4][4];
#pragma unroll
            for (int mt = 0; mt < 4; mt++)
                ldsm_x4(a[mt], Wb + mt * 16 * 80 + ks * 32 + aoff);
            uint32_t bf[4][2];
#pragma unroll
            for (int nt = 0; nt < 4; nt++)
                ldsm_x2(bf[nt], Ub + nt * 8 * 80 + ks * 32 + boff);
#pragma unroll
            for (int nt = 0; nt < 4; nt++)
#pragma unroll
                for (int mt = 0; mt < 4; mt++)
                    mma16816(acc[mt][nt], a[mt], bf[nt]);
        }
        __syncthreads();
    }

    // column max over n (warp 32 n), cross-warp over wn via red
#pragma unroll
    for (int mt = 0; mt < 4; mt++) {
        float m0 = -3.4e38f, m1 = -3.4e38f;
#pragma unroll
        for (int nt = 0; nt < 4; nt++) {
            m0 = fmaxf(m0, fmaxf(acc[mt][nt][0], acc[mt][nt][1]));
            m1 = fmaxf(m1, fmaxf(acc[mt][nt][2], acc[mt][nt][3]));
        }
        m0 = fmaxf(m0, __shfl_xor_sync(0xffffffffu, m0, 1));
        m0 = fmaxf(m0, __shfl_xor_sync(0xffffffffu, m0, 2));
        m1 = fmaxf(m1, __shfl_xor_sync(0xffffffffu, m1, 1));
        m1 = fmaxf(m1, __shfl_xor_sync(0xffffffffu, m1, 2));
        if ((lane & 3) == 0) {
            int ol = wm * 64 + mt * 16 + (lane >> 2);
            red[ol * 5 + wn]       = m0;
            red[(ol + 8) * 5 + wn] = m1;
        }
    }
    __syncthreads();
    if (tid < 128) {
        float m = fmaxf(fmaxf(red[tid * 5], red[tid * 5 + 1]),
                        fmaxf(red[tid * 5 + 2], red[tid * 5 + 3]));
        g_pmax[blockIdx.x * 1024 + o0 + tid] = m + csb[o0 + tid];
    }
}

// ---------------------------------------------------------------- D1: global max over 32 partials
__global__ void k_rmax() {
    int o = blockIdx.x * 128 + threadIdx.x;
    float m = g_pmax[o];
#pragma unroll
    for (int j = 1; j < 32; j++) m = fmaxf(m, g_pmax[j * 1024 + o]);
    g_rm[o] = m;
}

// ---------------------------------------------------------------- D2: lin1 + tanh (warp/output)
__global__ void k_lin1(const float* __restrict__ w1, const float* __restrict__ b1) {
    int lane = threadIdx.x & 31;
    int j = blockIdx.x * 4 + (threadIdx.x >> 5);
    float s = 0.f;
    const float* wr = w1 + (size_t)j * 1024;
#pragma unroll
    for (int i = 0; i < 32; i++)
        s = fmaf(g_rm[i * 32 + lane], wr[i * 32 + lane], s);
#pragma unroll
    for (int d = 16; d > 0; d >>= 1) s += __shfl_xor_sync(0xffffffffu, s, d);
    if (lane == 0) g_h[j] = tanhf(s + b1[j]);
}

// ---------------------------------------------------------------- D3: lin2
__global__ void k_lin2(const float* __restrict__ w2, const float* __restrict__ b2,
                       float* __restrict__ out) {
    __shared__ float p0s[256], p1s[256];
    int t = threadIdx.x;
    float p0 = 0.f, p1 = 0.f;
    for (int i = t; i < 2048; i += 256) {
        float h = g_h[i];
        p0 = fmaf(h, w2[i], p0);
        p1 = fmaf(h, w2[2048 + i], p1);
    }
    p0s[t] = p0; p1s[t] = p1;
    __syncthreads();
    for (int s = 128; s > 0; s >>= 1) {
        if (t < s) { p0s[t] += p0s[t + s]; p1s[t] += p1s[t + s]; }
        __syncthreads();
    }
    if (t == 0) { out[0] = p0s[0] + b2[0]; out[1] = p1s[0] + b2[1]; }
}

// ----------------------------------------------------------------
extern "C" void kernel_launch(void* const* d_in, const int* in_sizes, int n_in,
                              void* d_out, int out_size) {
    const int*   words = (const int*)d_in[0];
    const int*   wic   = (const int*)d_in[1];
    const float* we    = (const float*)d_in[2];
    const float* ce    = (const float*)d_in[3];
    const float* cw    = (const float*)d_in[4];
    const float* cb    = (const float*)d_in[5];
    const float* ws    = (const float*)d_in[6];
    const float* csb   = (const float*)d_in[7];
    const float* w1    = (const float*)d_in[8];
    const float* b1    = (const float*)d_in[9];
    const float* w2    = (const float*)d_in[10];
    const float* b2    = (const float*)d_in[11];
    float* out = (float*)d_out;

    static int smem_set = 0;
    if (!smem_set) {
        cudaFuncSetAttribute(k_conv, cudaFuncAttributeMaxDynamicSharedMemorySize,
                             CONV_SMEM);
        smem_set = 1;
    }

    k_prep_ce<<<256, 256>>>(ce);
    k_prep_w <<<dim3(32, 4), 128>>>(cw);
    k_word   <<<4096, 128>>>(words, we);
    k_repack <<<4096, 256>>>(ws);
    k_conv   <<<dim3(512, 4), 512, CONV_SMEM>>>(wic, cb);
    k_sent   <<<dim3(32, 8), 256>>>(csb);
    k_rmax   <<<8, 128>>>();
    k_lin1   <<<512, 128>>>(w1, b1);
    k_lin2   <<<1, 256>>>(w2, b2, out);
}

// round 9
// speedup vs baseline: 10.0190x; 1.1577x over previous
#include <cuda_runtime.h>
#include <cuda_fp16.h>
#include <stdint.h>
#include <math.h>

// ---------------------------------------------------------------- scratch
__device__ __half g_uh[4096 * 1024];    // [N][v_word(512) | v_wch(512)] fp16
__device__ __half g_wch[1024 * 1024];   // repacked conv_sent_w[:,:,1] fp16
__device__ float g_pmax[32 * 1024];
__device__ float g_rm[1024];
__device__ float g_h[2048];
__device__ __half g_ceh[256 * 512];     // char emb transposed [c][pos*16+ic]
// prepacked conv weights (fp16, x64): [og(4)][stage(16)] blocks of 30720B
//   block = [tap(3)][oc(128)] rows of 80B (32 fp16 + 16B pad)
__device__ uint4 g_wA4[4 * 16 * 30720 / 16];

// ---------------------------------------------------------------- helpers
__device__ __forceinline__ uint32_t smem_u32(const void* p) {
    uint32_t a;
    asm("{ .reg .u64 t; cvta.to.shared.u64 t, %1; cvt.u32.u64 %0, t; }"
        : "=r"(a) : "l"(p));
    return a;
}
__device__ __forceinline__ void cp16(uint32_t dst, const void* src) {
    asm volatile("cp.async.cg.shared.global [%0], [%1], 16;"
                 :: "r"(dst), "l"(src) : "memory");
}
__device__ __forceinline__ void cp_commit() {
    asm volatile("cp.async.commit_group;" ::: "memory");
}
__device__ __forceinline__ void cp_wait0() {
    asm volatile("cp.async.wait_group 0;" ::: "memory");
}
__device__ __forceinline__ void cp_wait1() {
    asm volatile("cp.async.wait_group 1;" ::: "memory");
}
__device__ __forceinline__ void ldsm_x4(uint32_t* r, uint32_t addr) {
    asm volatile("ldmatrix.sync.aligned.m8n8.x4.shared.b16 {%0,%1,%2,%3}, [%4];"
                 : "=r"(r[0]), "=r"(r[1]), "=r"(r[2]), "=r"(r[3]) : "r"(addr));
}
__device__ __forceinline__ void ldsm_x2(uint32_t* r, uint32_t addr) {
    asm volatile("ldmatrix.sync.aligned.m8n8.x2.shared.b16 {%0,%1}, [%2];"
                 : "=r"(r[0]), "=r"(r[1]) : "r"(addr));
}
__device__ __forceinline__ void mma16816(float* c, const uint32_t* a, const uint32_t* b) {
    asm volatile(
        "mma.sync.aligned.m16n8k16.row.col.f32.f16.f16.f32 "
        "{%0,%1,%2,%3}, {%4,%5,%6,%7}, {%8,%9}, {%0,%1,%2,%3};"
        : "+f"(c[0]), "+f"(c[1]), "+f"(c[2]), "+f"(c[3])
        : "r"(a[0]), "r"(a[1]), "r"(a[2]), "r"(a[3]), "r"(b[0]), "r"(b[1]));
}

// ---------------------------------------------------------------- prepacks
__global__ void k_prep_ce(const float* __restrict__ ce) {
    int c = blockIdx.x;
    for (int d = threadIdx.x; d < 512; d += 256) {
        float v = (c == 0) ? 0.f : ce[c * 512 + d] * 64.f;
        g_ceh[c * 512 + (d & 31) * 16 + (d >> 5)] = __float2half(v);
    }
}

// conv weights -> [og][stage16]: [tap3][oc128] rows of 40 fp16 (32 data + pad)
__global__ void k_prep_w(const float* __restrict__ cw) {
    int s  = blockIdx.x;           // 0..15
    int og = blockIdx.y;           // 0..3
    int oc = threadIdx.x;          // 0..127
    __half* gb = (__half*)g_wA4;
    size_t base0 = ((size_t)og * 16 + s) * 15360;
#pragma unroll
    for (int t = 0; t < 3; t++) {
        size_t rb = base0 + (size_t)t * 5120 + oc * 40;
#pragma unroll
        for (int i = 0; i < 32; i++) {
            float w = cw[(size_t)(og * 128 + oc) * 1536 + (size_t)(s * 32 + i) * 3 + t] * 64.f;
            gb[rb + i] = __float2half(w);
        }
#pragma unroll
        for (int i = 32; i < 40; i++) gb[rb + i] = __half(0.f);
    }
}

// ---------------------------------------------------------------- A: v_word gather (fp16)
__global__ void k_word(const int* __restrict__ words, const float* __restrict__ we) {
    int n = blockIdx.x;
    int w = words[n];
    float4 v = make_float4(0.f, 0.f, 0.f, 0.f);
    if (w != 0) v = ((const float4*)(we + (size_t)w * 512))[threadIdx.x];
    __half2* dst = (__half2*)(g_uh + (size_t)n * 1024) + threadIdx.x * 2;
    dst[0] = __floats2half2_rn(v.x, v.y);
    dst[1] = __floats2half2_rn(v.z, v.w);
}

// ---------------------------------------------------------------- B: HMMA conv v2
// CTA = 128 oc x 8 words, 256 thr (8 warps: wm2 x wn4); warp = 64oc x 64pos.
// 16 stages of 32 ic (2 chars); 3-buffer ring, 1 barrier/stage.
// Buffer: A 30720B [tap3][oc128]x80B ; X 26112B [sub16 = w8*q2][pos34]x48B
#define ABYTES2 30720
#define XBYTES2 26112
#define BUFB2   (ABYTES2 + XBYTES2)
#define NS2     16
#define CONV_SMEM (3 * BUFB2 + 1024)

__global__ __launch_bounds__(256, 1) void k_conv(
    const int* __restrict__ wic, const float* __restrict__ cb) {
    extern __shared__ char sm[];
    uint32_t sb = smem_u32(sm);
    int tid = threadIdx.x;
    int lane = tid & 31, w = tid >> 5;
    int wm = w >> 2, wn = w & 3;          // wm: oc half, wn: word pair
    int nb0 = blockIdx.x * 8;
    int og  = blockIdx.y;
    int oc0 = og * 128;
    int* cs = (int*)(sm + 3 * BUFB2);     // [8][32]

    cs[tid] = wic[(nb0 + (tid >> 5)) * 32 + (tid & 31)];
    // zero halo rows (pos rows 0/33) of all 16 subtiles x 3 buffers
    for (int e = tid; e < 288; e += 256) {
        int buf = e / 96, r = e % 96;
        int sub = r / 6, rem = r % 6, row = (rem >= 3) ? 33 : 0, q = rem % 3;
        *(uint4*)(sm + buf * BUFB2 + ABYTES2 + sub * 1632 + row * 48 + q * 16) =
            make_uint4(0, 0, 0, 0);
    }
    __syncthreads();

    const char* gA = (const char*)g_wA4 + (size_t)og * 16 * ABYTES2;

    auto issue = [&](int s, int b) {
        uint32_t Ab = sb + b * BUFB2;
        const char* src = gA + (size_t)s * ABYTES2;
        for (int i = tid; i < ABYTES2 / 16; i += 256)
            cp16(Ab + i * 16, src + i * 16);
        uint32_t Xb = Ab + ABYTES2;
#pragma unroll
        for (int it = 0; it < 4; it++) {
            int e = tid + it * 256;            // 0..1023
            int sub = e >> 6, r = (e >> 1) & 31, h = e & 1;
            int ch = cs[(sub >> 1) * 32 + s * 2 + (sub & 1)];
            cp16(Xb + sub * 1632 + (r + 1) * 48 + h * 16,
                 g_ceh + ch * 512 + r * 16 + h * 8);
        }
        cp_commit();
    };

    float acc[4][8][4];
#pragma unroll
    for (int i = 0; i < 4; i++)
#pragma unroll
        for (int j = 0; j < 8; j++)
#pragma unroll
            for (int q = 0; q < 4; q++) acc[i][j][q] = 0.f;

    uint32_t aoff = (uint32_t)((lane & 15) * 80 + (lane >> 4) * 16);
    // B x4: lanes0-7 ntA col0, 8-15 ntA col16, 16-23 ntB col0, 24-31 ntB col16
    uint32_t brow = (uint32_t)(((lane >> 4) & 1) * 8 + (lane & 7));
    uint32_t bcol = (uint32_t)(((lane >> 3) & 1) * 16);

    issue(0, 0);
    issue(1, 1);
    for (int s = 0; s < NS2; s++) {
        if (s == NS2 - 1) cp_wait0(); else cp_wait1();
        __syncthreads();
        if (s + 2 < NS2) issue(s + 2, (s + 2) % 3);

        int b = s % 3;
        uint32_t Ab = sb + b * BUFB2;
        uint32_t Xb = Ab + ABYTES2;
#pragma unroll
        for (int t = 0; t < 3; t++) {
#pragma unroll
            for (int q = 0; q < 2; q++) {
                uint32_t ah[4][4];
#pragma unroll
                for (int mt = 0; mt < 4; mt++)
                    ldsm_x4(ah[mt], Ab + t * 10240 +
                            (wm * 64 + mt * 16) * 80 + q * 32 + aoff);
                uint32_t bf[4][4];
#pragma unroll
                for (int jp = 0; jp < 4; jp++) {
                    int wj = jp >> 1, lp = jp & 1;   // word sub, pos half
                    uint32_t sub = (uint32_t)((wn * 2 + wj) * 2 + q);
                    ldsm_x4(bf[jp], Xb + sub * 1632 +
                            (lp * 16 + t + brow) * 48 + bcol);
                }
#pragma unroll
                for (int jp = 0; jp < 4; jp++)
#pragma unroll
                    for (int mt = 0; mt < 4; mt++) {
                        mma16816(acc[mt][jp * 2],     ah[mt], bf[jp] + 0);
                        mma16816(acc[mt][jp * 2 + 1], ah[mt], bf[jp] + 2);
                    }
            }
        }
        __syncthreads();
    }

    // ---- epilogue: per word (2/warp) maxpool over 32 pos, bias, store fp16
#pragma unroll
    for (int j = 0; j < 2; j++) {
        int n = nb0 + wn * 2 + j;
#pragma unroll
        for (int mt = 0; mt < 4; mt++) {
            float m0 = -3.4e38f, m1 = -3.4e38f;
#pragma unroll
            for (int nt = j * 4; nt < j * 4 + 4; nt++) {
                m0 = fmaxf(m0, fmaxf(acc[mt][nt][0], acc[mt][nt][1]));
                m1 = fmaxf(m1, fmaxf(acc[mt][nt][2], acc[mt][nt][3]));
            }
            m0 = fmaxf(m0, __shfl_xor_sync(0xffffffffu, m0, 1));
            m0 = fmaxf(m0, __shfl_xor_sync(0xffffffffu, m0, 2));
            m1 = fmaxf(m1, __shfl_xor_sync(0xffffffffu, m1, 1));
            m1 = fmaxf(m1, __shfl_xor_sync(0xffffffffu, m1, 2));
            if ((lane & 3) == 0) {
                int row = lane >> 2;
                int oc = oc0 + wm * 64 + mt * 16 + row;
                g_uh[(size_t)n * 1024 + 512 + oc] =
                    __float2half(m0 * (1.f / 4096.f) + cb[oc]);
                g_uh[(size_t)n * 1024 + 512 + oc + 8] =
                    __float2half(m1 * (1.f / 4096.f) + cb[oc + 8]);
            }
        }
    }
}

// ---------------------------------------------------------------- C1: repack sent W (fp16)
__global__ void k_repack(const float* __restrict__ ws) {
    int i = blockIdx.x * 256 + threadIdx.x;
    g_wch[i] = __float2half(ws[(size_t)i * 3 + 1]);
}

// ---------------------------------------------------------------- C2: HMMA r = u@Wc^T + colmax
__global__ __launch_bounds__(256, 2) void k_sent(const float* __restrict__ csb) {
    __shared__ __align__(16) char smem[2 * 20480];
    __shared__ float red[128 * 5];
    uint32_t sb = smem_u32(smem);
    int tid = threadIdx.x;
    int lane = tid & 31, w = tid >> 5;
    int wm = w >> 2, wn = w & 3;
    int nb = blockIdx.x * 128;
    int o0 = blockIdx.y * 128;

    auto issue = [&](int kc, int b) {
        uint32_t Ub = sb + b * 20480;
#pragma unroll
        for (int it = 0; it < 2; it++) {
            int e = tid + it * 256;
            int r = e >> 2, q = e & 3;
            cp16(Ub + r * 80 + q * 16, g_uh + (size_t)(nb + r) * 1024 + kc * 32 + q * 8);
        }
        uint32_t Wb = Ub + 10240;
#pragma unroll
        for (int it = 0; it < 2; it++) {
            int e = tid + it * 256;
            int r = e >> 2, q = e & 3;
            cp16(Wb + r * 80 + q * 16, g_wch + (size_t)(o0 + r) * 1024 + kc * 32 + q * 8);
        }
        cp_commit();
    };

    float acc[4][4][4];
#pragma unroll
    for (int i = 0; i < 4; i++)
#pragma unroll
        for (int j = 0; j < 4; j++)
#pragma unroll
            for (int q = 0; q < 4; q++) acc[i][j][q] = 0.f;

    uint32_t aoff = (uint32_t)((wm * 64 + (lane & 15)) * 80 + (lane >> 4) * 16);
    uint32_t boff = (uint32_t)((wn * 32 + (lane & 7)) * 80 + ((lane >> 3) & 1) * 16);

    issue(0, 0);
    for (int kc = 0; kc < 32; kc++) {
        int b = kc & 1;
        if (kc < 31) { issue(kc + 1, b ^ 1); cp_wait1(); } else cp_wait0();
        __syncthreads();
        uint32_t Ub = sb + b * 20480;
        uint32_t Wb = Ub + 10240;
#pragma unroll
        for (int ks = 0; ks < 2; ks++) {
            uint32_t a[4][4];
#pragma unroll
            for (int mt = 0; mt < 4; mt++)
                ldsm_x4(a[mt], Wb + mt * 16 * 80 + ks * 32 + aoff);
            uint32_t bf[4][2];
#pragma unroll
            for (int nt = 0; nt < 4; nt++)
                ldsm_x2(bf[nt], Ub + nt * 8 * 80 + ks * 32 + boff);
#pragma unroll
            for (int nt = 0; nt < 4; nt++)
#pragma unroll
                for (int mt = 0; mt < 4; mt++)
                    mma16816(acc[mt][nt], a[mt], bf[nt]);
        }
        __syncthreads();
    }

#pragma unroll
    for (int mt = 0; mt < 4; mt++) {
        float m0 = -3.4e38f, m1 = -3.4e38f;
#pragma unroll
        for (int nt = 0; nt < 4; nt++) {
            m0 = fmaxf(m0, fmaxf(acc[mt][nt][0], acc[mt][nt][1]));
            m1 = fmaxf(m1, fmaxf(acc[mt][nt][2], acc[mt][nt][3]));
        }
        m0 = fmaxf(m0, __shfl_xor_sync(0xffffffffu, m0, 1));
        m0 = fmaxf(m0, __shfl_xor_sync(0xffffffffu, m0, 2));
        m1 = fmaxf(m1, __shfl_xor_sync(0xffffffffu, m1, 1));
        m1 = fmaxf(m1, __shfl_xor_sync(0xffffffffu, m1, 2));
        if ((lane & 3) == 0) {
            int ol = wm * 64 + mt * 16 + (lane >> 2);
            red[ol * 5 + wn]       = m0;
            red[(ol + 8) * 5 + wn] = m1;
        }
    }
    __syncthreads();
    if (tid < 128) {
        float m = fmaxf(fmaxf(red[tid * 5], red[tid * 5 + 1]),
                        fmaxf(red[tid * 5 + 2], red[tid * 5 + 3]));
        g_pmax[blockIdx.x * 1024 + o0 + tid] = m + csb[o0 + tid];
    }
}

// ---------------------------------------------------------------- D1: global max
__global__ void k_rmax() {
    int o = blockIdx.x * 128 + threadIdx.x;
    float m = g_pmax[o];
#pragma unroll
    for (int j = 1; j < 32; j++) m = fmaxf(m, g_pmax[j * 1024 + o]);
    g_rm[o] = m;
}

// ---------------------------------------------------------------- D2: lin1 + tanh
__global__ void k_lin1(const float* __restrict__ w1, const float* __restrict__ b1) {
    int lane = threadIdx.x & 31;
    int j = blockIdx.x * 4 + (threadIdx.x >> 5);
    float s = 0.f;
    const float* wr = w1 + (size_t)j * 1024;
#pragma unroll
    for (int i = 0; i < 32; i++)
        s = fmaf(g_rm[i * 32 + lane], wr[i * 32 + lane], s);
#pragma unroll
    for (int d = 16; d > 0; d >>= 1) s += __shfl_xor_sync(0xffffffffu, s, d);
    if (lane == 0) g_h[j] = tanhf(s + b1[j]);
}

// ---------------------------------------------------------------- D3: lin2
__global__ void k_lin2(const float* __restrict__ w2, const float* __restrict__ b2,
                       float* __restrict__ out) {
    __shared__ float p0s[256], p1s[256];
    int t = threadIdx.x;
    float p0 = 0.f, p1 = 0.f;
    for (int i = t; i < 2048; i += 256) {
        float h = g_h[i];
        p0 = fmaf(h, w2[i], p0);
        p1 = fmaf(h, w2[2048 + i], p1);
    }
    p0s[t] = p0; p1s[t] = p1;
    __syncthreads();
    for (int s = 128; s > 0; s >>= 1) {
        if (t < s) { p0s[t] += p0s[t + s]; p1s[t] += p1s[t + s]; }
        __syncthreads();
    }
    if (t == 0) { out[0] = p0s[0] + b2[0]; out[1] = p1s[0] + b2[1]; }
}

// ----------------------------------------------------------------
extern "C" void kernel_launch(void* const* d_in, const int* in_sizes, int n_in,
                              void* d_out, int out_size) {
    const int*   words = (const int*)d_in[0];
    const int*   wic   = (const int*)d_in[1];
    const float* we    = (const float*)d_in[2];
    const float* ce    = (const float*)d_in[3];
    const float* cw    = (const float*)d_in[4];
    const float* cb    = (const float*)d_in[5];
    const float* ws    = (const float*)d_in[6];
    const float* csb   = (const float*)d_in[7];
    const float* w1    = (const float*)d_in[8];
    const float* b1    = (const float*)d_in[9];
    const float* w2    = (const float*)d_in[10];
    const float* b2    = (const float*)d_in[11];
    float* out = (float*)d_out;

    static int smem_set = 0;
    if (!smem_set) {
        cudaFuncSetAttribute(k_conv, cudaFuncAttributeMaxDynamicSharedMemorySize,
                             CONV_SMEM);
        smem_set = 1;
    }

    k_prep_ce<<<256, 256>>>(ce);
    k_prep_w <<<dim3(16, 4), 128>>>(cw);
    k_word   <<<4096, 128>>>(words, we);
    k_repack <<<4096, 256>>>(ws);
    k_conv   <<<dim3(512, 4), 256, CONV_SMEM>>>(wic, cb);
    k_sent   <<<dim3(32, 8), 256>>>(csb);
    k_rmax   <<<8, 128>>>();
    k_lin1   <<<512, 128>>>(w1, b1);
    k_lin2   <<<1, 256>>>(w2, b2, out);
}

// round 10
// speedup vs baseline: 10.3340x; 1.0314x over previous
#include <cuda_runtime.h>
#include <cuda_fp16.h>
#include <stdint.h>
#include <math.h>

// ---------------------------------------------------------------- scratch
__device__ __half g_uh[4096 * 1024];    // [N][v_word(512) | v_wch(512)] fp16
__device__ __half g_wch[1024 * 1024];   // repacked conv_sent_w[:,:,1] fp16
__device__ float g_pmax[32 * 1024];
__device__ float g_rm[1024];
__device__ float g_h[2048];
__device__ __half g_ceh[256 * 512];     // char emb transposed [c][pos*16+ic]
// prepacked conv weights (fp16, x64): [og(4)][stage(8)] blocks of 55296B
//   block = [tap(3)][oc(128)] rows of 144B (64 fp16 + 16B pad)
__device__ uint4 g_wA4[4 * 8 * 55296 / 16];

// ---------------------------------------------------------------- helpers
__device__ __forceinline__ uint32_t smem_u32(const void* p) {
    uint32_t a;
    asm("{ .reg .u64 t; cvta.to.shared.u64 t, %1; cvt.u32.u64 %0, t; }"
        : "=r"(a) : "l"(p));
    return a;
}
__device__ __forceinline__ void cp16(uint32_t dst, const void* src) {
    asm volatile("cp.async.cg.shared.global [%0], [%1], 16;"
                 :: "r"(dst), "l"(src) : "memory");
}
__device__ __forceinline__ void cp_commit() {
    asm volatile("cp.async.commit_group;" ::: "memory");
}
__device__ __forceinline__ void cp_wait0() {
    asm volatile("cp.async.wait_group 0;" ::: "memory");
}
__device__ __forceinline__ void cp_wait1() {
    asm volatile("cp.async.wait_group 1;" ::: "memory");
}
__device__ __forceinline__ void ldsm_x4(uint32_t* r, uint32_t addr) {
    asm volatile("ldmatrix.sync.aligned.m8n8.x4.shared.b16 {%0,%1,%2,%3}, [%4];"
                 : "=r"(r[0]), "=r"(r[1]), "=r"(r[2]), "=r"(r[3]) : "r"(addr));
}
__device__ __forceinline__ void ldsm_x2(uint32_t* r, uint32_t addr) {
    asm volatile("ldmatrix.sync.aligned.m8n8.x2.shared.b16 {%0,%1}, [%2];"
                 : "=r"(r[0]), "=r"(r[1]) : "r"(addr));
}
__device__ __forceinline__ void mma16816(float* c, const uint32_t* a, const uint32_t* b) {
    asm volatile(
        "mma.sync.aligned.m16n8k16.row.col.f32.f16.f16.f32 "
        "{%0,%1,%2,%3}, {%4,%5,%6,%7}, {%8,%9}, {%0,%1,%2,%3};"
        : "+f"(c[0]), "+f"(c[1]), "+f"(c[2]), "+f"(c[3])
        : "r"(a[0]), "r"(a[1]), "r"(a[2]), "r"(a[3]), "r"(b[0]), "r"(b[1]));
}

// ---------------------------------------------------------------- fused prep
// blocks [0,256): char emb transpose+fp16; [256,288): conv W pack;
// [288,4384): sent-W repack; [4384,6432): word gather.
__global__ void k_prep(const float* __restrict__ ce, const float* __restrict__ cw,
                       const float* __restrict__ ws, const int* __restrict__ words,
                       const float* __restrict__ we) {
    int b = blockIdx.x, tid = threadIdx.x;
    if (b < 256) {
        int c = b;
        for (int d = tid; d < 512; d += 256) {
            float v = (c == 0) ? 0.f : ce[c * 512 + d] * 64.f;
            g_ceh[c * 512 + (d & 31) * 16 + (d >> 5)] = __float2half(v);
        }
    } else if (b < 288) {
        int og = (b - 256) >> 3, s = (b - 256) & 7;
        int oc = tid >> 1, half = tid & 1;
        __half* gb = (__half*)g_wA4;
        size_t base = ((size_t)og * 8 + s) * 27648;   // halves (55296B/2)
#pragma unroll
        for (int t = 0; t < 3; t++) {
            size_t rb = base + (size_t)t * 9216 + oc * 72 + half * 32;
#pragma unroll
            for (int j = 0; j < 32; j++) {
                int i = half * 32 + j;
                float w = cw[(size_t)(og * 128 + oc) * 1536 +
                             (size_t)(s * 64 + i) * 3 + t] * 64.f;
                gb[rb + j] = __float2half(w);
            }
            if (half) {
#pragma unroll
                for (int j = 0; j < 8; j++) gb[base + (size_t)t * 9216 + oc * 72 + 64 + j] = __half(0.f);
            }
        }
    } else if (b < 4384) {
        size_t i = (size_t)(b - 288) * 256 + tid;
        g_wch[i] = __float2half(ws[i * 3 + 1]);
    } else {
        int n = (b - 4384) * 2 + (tid >> 7);
        int t128 = tid & 127;
        int w = words[n];
        float4 v = make_float4(0.f, 0.f, 0.f, 0.f);
        if (w != 0) v = ((const float4*)(we + (size_t)w * 512))[t128];
        __half2* dst = (__half2*)(g_uh + (size_t)n * 1024) + t128 * 2;
        dst[0] = __floats2half2_rn(v.x, v.y);
        dst[1] = __floats2half2_rn(v.z, v.w);
    }
}

// ---------------------------------------------------------------- B: HMMA conv v3
// CTA = 128 oc x 8 words, 256 thr (8 warps: wm2 x wn4); warp = 64oc x 64pos.
// 8 stages of 64 ic (4 chars); double buffer, 2 barriers/stage.
// Buffer: A 55296B [tap3][oc128]x144B ; X 52224B [sub32 = w8*q4][pos34]x48B
#define ABYTES3 55296
#define XBYTES3 52224
#define BUFB3   (ABYTES3 + XBYTES3)
#define NS3     8
#define CONV_SMEM (2 * BUFB3 + 1024)

__global__ __launch_bounds__(256, 1) void k_conv(
    const int* __restrict__ wic, const float* __restrict__ cb) {
    extern __shared__ char sm[];
    uint32_t sb = smem_u32(sm);
    int tid = threadIdx.x;
    int lane = tid & 31, w = tid >> 5;
    int wm = w >> 2, wn = w & 3;
    int nb0 = blockIdx.x * 8;
    int og  = blockIdx.y;
    int oc0 = og * 128;
    int* cs = (int*)(sm + 2 * BUFB3);     // [8][32]

    cs[tid] = wic[(nb0 + (tid >> 5)) * 32 + (tid & 31)];
    // zero halo rows (pos 0/33) of 32 subtiles x 2 buffers
    for (int e = tid; e < 384; e += 256) {
        int buf = e / 192, r = e % 192;
        int sub = r / 6, rem = r % 6, row = (rem >= 3) ? 33 : 0, q = rem % 3;
        *(uint4*)(sm + buf * BUFB3 + ABYTES3 + sub * 1632 + row * 48 + q * 16) =
            make_uint4(0, 0, 0, 0);
    }
    __syncthreads();

    const char* gA = (const char*)g_wA4 + (size_t)og * 8 * ABYTES3;

    auto issue = [&](int s, int b) {
        uint32_t Ab = sb + b * BUFB3;
        const char* src = gA + (size_t)s * ABYTES3;
        for (int i = tid; i < ABYTES3 / 16; i += 256)
            cp16(Ab + i * 16, src + i * 16);
        uint32_t Xb = Ab + ABYTES3;
#pragma unroll
        for (int it = 0; it < 8; it++) {
            int e = tid + it * 256;            // 0..2047
            int sub = e >> 6, r = (e >> 1) & 31, h = e & 1;
            int ch = cs[(sub >> 2) * 32 + s * 4 + (sub & 3)];
            cp16(Xb + sub * 1632 + (r + 1) * 48 + h * 16,
                 g_ceh + ch * 512 + r * 16 + h * 8);
        }
        cp_commit();
    };

    float acc[4][8][4];
#pragma unroll
    for (int i = 0; i < 4; i++)
#pragma unroll
        for (int j = 0; j < 8; j++)
#pragma unroll
            for (int q = 0; q < 4; q++) acc[i][j][q] = 0.f;

    uint32_t aoff = (uint32_t)((lane & 15) * 144 + (lane >> 4) * 16);
    uint32_t brow = (uint32_t)(((lane >> 4) & 1) * 8 + (lane & 7));
    uint32_t bcol = (uint32_t)(((lane >> 3) & 1) * 16);

    issue(0, 0);
    issue(1, 1);
    for (int s = 0; s < NS3; s++) {
        if (s == NS3 - 1) cp_wait0(); else cp_wait1();
        __syncthreads();

        int b = s & 1;
        uint32_t Ab = sb + b * BUFB3;
        uint32_t Xb = Ab + ABYTES3;
#pragma unroll
        for (int t = 0; t < 3; t++) {
#pragma unroll
            for (int q = 0; q < 4; q++) {
                uint32_t ah[4][4];
#pragma unroll
                for (int mt = 0; mt < 4; mt++)
                    ldsm_x4(ah[mt], Ab + t * 18432 +
                            (wm * 64 + mt * 16) * 144 + q * 32 + aoff);
                uint32_t bf[4][4];
#pragma unroll
                for (int jp = 0; jp < 4; jp++) {
                    int wj = jp >> 1, lp = jp & 1;
                    uint32_t sub = (uint32_t)((wn * 2 + wj) * 4 + q);
                    ldsm_x4(bf[jp], Xb + sub * 1632 +
                            (lp * 16 + t + brow) * 48 + bcol);
                }
#pragma unroll
                for (int jp = 0; jp < 4; jp++)
#pragma unroll
                    for (int mt = 0; mt < 4; mt++) {
                        mma16816(acc[mt][jp * 2],     ah[mt], bf[jp] + 0);
                        mma16816(acc[mt][jp * 2 + 1], ah[mt], bf[jp] + 2);
                    }
            }
        }
        __syncthreads();
        if (s + 2 < NS3) issue(s + 2, b);
    }

    // ---- epilogue: per word (2/warp) maxpool over 32 pos, bias, store fp16
#pragma unroll
    for (int j = 0; j < 2; j++) {
        int n = nb0 + wn * 2 + j;
#pragma unroll
        for (int mt = 0; mt < 4; mt++) {
            float m0 = -3.4e38f, m1 = -3.4e38f;
#pragma unroll
            for (int nt = j * 4; nt < j * 4 + 4; nt++) {
                m0 = fmaxf(m0, fmaxf(acc[mt][nt][0], acc[mt][nt][1]));
                m1 = fmaxf(m1, fmaxf(acc[mt][nt][2], acc[mt][nt][3]));
            }
            m0 = fmaxf(m0, __shfl_xor_sync(0xffffffffu, m0, 1));
            m0 = fmaxf(m0, __shfl_xor_sync(0xffffffffu, m0, 2));
            m1 = fmaxf(m1, __shfl_xor_sync(0xffffffffu, m1, 1));
            m1 = fmaxf(m1, __shfl_xor_sync(0xffffffffu, m1, 2));
            if ((lane & 3) == 0) {
                int row = lane >> 2;
                int oc = oc0 + wm * 64 + mt * 16 + row;
                g_uh[(size_t)n * 1024 + 512 + oc] =
                    __float2half(m0 * (1.f / 4096.f) + cb[oc]);
                g_uh[(size_t)n * 1024 + 512 + oc + 8] =
                    __float2half(m1 * (1.f / 4096.f) + cb[oc + 8]);
            }
        }
    }
}

// ---------------------------------------------------------------- C2: HMMA r = u@Wc^T + colmax
__global__ __launch_bounds__(256, 2) void k_sent(const float* __restrict__ csb) {
    __shared__ __align__(16) char smem[2 * 20480];
    __shared__ float red[128 * 5];
    uint32_t sb = smem_u32(smem);
    int tid = threadIdx.x;
    int lane = tid & 31, w = tid >> 5;
    int wm = w >> 2, wn = w & 3;
    int nb = blockIdx.x * 128;
    int o0 = blockIdx.y * 128;

    auto issue = [&](int kc, int b) {
        uint32_t Ub = sb + b * 20480;
#pragma unroll
        for (int it = 0; it < 2; it++) {
            int e = tid + it * 256;
            int r = e >> 2, q = e & 3;
            cp16(Ub + r * 80 + q * 16, g_uh + (size_t)(nb + r) * 1024 + kc * 32 + q * 8);
        }
        uint32_t Wb = Ub + 10240;
#pragma unroll
        for (int it = 0; it < 2; it++) {
            int e = tid + it * 256;
            int r = e >> 2, q = e & 3;
            cp16(Wb + r * 80 + q * 16, g_wch + (size_t)(o0 + r) * 1024 + kc * 32 + q * 8);
        }
        cp_commit();
    };

    float acc[4][4][4];
#pragma unroll
    for (int i = 0; i < 4; i++)
#pragma unroll
        for (int j = 0; j < 4; j++)
#pragma unroll
            for (int q = 0; q < 4; q++) acc[i][j][q] = 0.f;

    uint32_t aoff = (uint32_t)((wm * 64 + (lane & 15)) * 80 + (lane >> 4) * 16);
    uint32_t boff = (uint32_t)((wn * 32 + (lane & 7)) * 80 + ((lane >> 3) & 1) * 16);

    issue(0, 0);
    for (int kc = 0; kc < 32; kc++) {
        int b = kc & 1;
        if (kc < 31) { issue(kc + 1, b ^ 1); cp_wait1(); } else cp_wait0();
        __syncthreads();
        uint32_t Ub = sb + b * 20480;
        uint32_t Wb = Ub + 10240;
#pragma unroll
        for (int ks = 0; ks < 2; ks++) {
            uint32_t a[4][4];
#pragma unroll
            for (int mt = 0; mt < 4; mt++)
                ldsm_x4(a[mt], Wb + mt * 16 * 80 + ks * 32 + aoff);
            uint32_t bf[4][2];
#pragma unroll
            for (int nt = 0; nt < 4; nt++)
                ldsm_x2(bf[nt], Ub + nt * 8 * 80 + ks * 32 + boff);
#pragma unroll
            for (int nt = 0; nt < 4; nt++)
#pragma unroll
                for (int mt = 0; mt < 4; mt++)
                    mma16816(acc[mt][nt], a[mt], bf[nt]);
        }
        __syncthreads();
    }

#pragma unroll
    for (int mt = 0; mt < 4; mt++) {
        float m0 = -3.4e38f, m1 = -3.4e38f;
#pragma unroll
        for (int nt = 0; nt < 4; nt++) {
            m0 = fmaxf(m0, fmaxf(acc[mt][nt][0], acc[mt][nt][1]));
            m1 = fmaxf(m1, fmaxf(acc[mt][nt][2], acc[mt][nt][3]));
        }
        m0 = fmaxf(m0, __shfl_xor_sync(0xffffffffu, m0, 1));
        m0 = fmaxf(m0, __shfl_xor_sync(0xffffffffu, m0, 2));
        m1 = fmaxf(m1, __shfl_xor_sync(0xffffffffu, m1, 1));
        m1 = fmaxf(m1, __shfl_xor_sync(0xffffffffu, m1, 2));
        if ((lane & 3) == 0) {
            int ol = wm * 64 + mt * 16 + (lane >> 2);
            red[ol * 5 + wn]       = m0;
            red[(ol + 8) * 5 + wn] = m1;
        }
    }
    __syncthreads();
    if (tid < 128) {
        float m = fmaxf(fmaxf(red[tid * 5], red[tid * 5 + 1]),
                        fmaxf(red[tid * 5 + 2], red[tid * 5 + 3]));
        g_pmax[blockIdx.x * 1024 + o0 + tid] = m + csb[o0 + tid];
    }
}

// ---------------------------------------------------------------- D1: global max
__global__ void k_rmax() {
    int o = blockIdx.x * 128 + threadIdx.x;
    float m = g_pmax[o];
#pragma unroll
    for (int j = 1; j < 32; j++) m = fmaxf(m, g_pmax[j * 1024 + o]);
    g_rm[o] = m;
}

// ---------------------------------------------------------------- D2: lin1 + tanh
__global__ void k_lin1(const float* __restrict__ w1, const float* __restrict__ b1) {
    int lane = threadIdx.x & 31;
    int j = blockIdx.x * 4 + (threadIdx.x >> 5);
    float s = 0.f;
    const float* wr = w1 + (size_t)j * 1024;
#pragma unroll
    for (int i = 0; i < 32; i++)
        s = fmaf(g_rm[i * 32 + lane], wr[i * 32 + lane], s);
#pragma unroll
    for (int d = 16; d > 0; d >>= 1) s += __shfl_xor_sync(0xffffffffu, s, d);
    if (lane == 0) g_h[j] = tanhf(s + b1[j]);
}

// ---------------------------------------------------------------- D3: lin2
__global__ void k_lin2(const float* __restrict__ w2, const float* __restrict__ b2,
                       float* __restrict__ out) {
    __shared__ float p0s[256], p1s[256];
    int t = threadIdx.x;
    float p0 = 0.f, p1 = 0.f;
    for (int i = t; i < 2048; i += 256) {
        float h = g_h[i];
        p0 = fmaf(h, w2[i], p0);
        p1 = fmaf(h, w2[2048 + i], p1);
    }
    p0s[t] = p0; p1s[t] = p1;
    __syncthreads();
    for (int s = 128; s > 0; s >>= 1) {
        if (t < s) { p0s[t] += p0s[t + s]; p1s[t] += p1s[t + s]; }
        __syncthreads();
    }
    if (t == 0) { out[0] = p0s[0] + b2[0]; out[1] = p1s[0] + b2[1]; }
}

// ----------------------------------------------------------------
extern "C" void kernel_launch(void* const* d_in, const int* in_sizes, int n_in,
                              void* d_out, int out_size) {
    const int*   words = (const int*)d_in[0];
    const int*   wic   = (const int*)d_in[1];
    const float* we    = (const float*)d_in[2];
    const float* ce    = (const float*)d_in[3];
    const float* cw    = (const float*)d_in[4];
    const float* cb    = (const float*)d_in[5];
    const float* ws    = (const float*)d_in[6];
    const float* csb   = (const float*)d_in[7];
    const float* w1    = (const float*)d_in[8];
    const float* b1    = (const float*)d_in[9];
    const float* w2    = (const float*)d_in[10];
    const float* b2    = (const float*)d_in[11];
    float* out = (float*)d_out;

    static int smem_set = 0;
    if (!smem_set) {
        cudaFuncSetAttribute(k_conv, cudaFuncAttributeMaxDynamicSharedMemorySize,
                             CONV_SMEM);
        smem_set = 1;
    }

    k_prep <<<6432, 256>>>(ce, cw, ws, words, we);
    k_conv <<<dim3(512, 4), 256, CONV_SMEM>>>(wic, cb);
    k_sent <<<dim3(32, 8), 256>>>(csb);
    k_rmax <<<8, 128>>>();
    k_lin1 <<<512, 128>>>(w1, b1);
    k_lin2 <<<1, 256>>>(w2, b2, out);
}

// round 11
// speedup vs baseline: 10.4796x; 1.0141x over previous
#include <cuda_runtime.h>
#include <cuda_fp16.h>
#include <stdint.h>
#include <math.h>

// ---------------------------------------------------------------- scratch
__device__ __half g_uh[4096 * 1024];    // [N][v_word(512) | v_wch(512)] fp16
__device__ __half g_wch[1024 * 1024];   // repacked conv_sent_w[:,:,1] fp16
__device__ float g_pmax[32 * 1024];
__device__ float g_rm[1024];
__device__ float g_h[2048];
__device__ __half g_ceh[256 * 512];     // char emb transposed [c][pos*16+ic]
// prepacked conv weights (fp16, x64): [og(4)][stage(8)] blocks of 55296B
__device__ uint4 g_wA4[4 * 8 * 55296 / 16];

// ---------------------------------------------------------------- helpers
__device__ __forceinline__ uint32_t smem_u32(const void* p) {
    uint32_t a;
    asm("{ .reg .u64 t; cvta.to.shared.u64 t, %1; cvt.u32.u64 %0, t; }"
        : "=r"(a) : "l"(p));
    return a;
}
__device__ __forceinline__ void cp16(uint32_t dst, const void* src) {
    asm volatile("cp.async.cg.shared.global [%0], [%1], 16;"
                 :: "r"(dst), "l"(src) : "memory");
}
__device__ __forceinline__ void cp_commit() {
    asm volatile("cp.async.commit_group;" ::: "memory");
}
__device__ __forceinline__ void cp_wait0() {
    asm volatile("cp.async.wait_group 0;" ::: "memory");
}
__device__ __forceinline__ void cp_wait1() {
    asm volatile("cp.async.wait_group 1;" ::: "memory");
}
__device__ __forceinline__ void ldsm_x4(uint32_t* r, uint32_t addr) {
    asm volatile("ldmatrix.sync.aligned.m8n8.x4.shared.b16 {%0,%1,%2,%3}, [%4];"
                 : "=r"(r[0]), "=r"(r[1]), "=r"(r[2]), "=r"(r[3]) : "r"(addr));
}
__device__ __forceinline__ void ldsm_x2(uint32_t* r, uint32_t addr) {
    asm volatile("ldmatrix.sync.aligned.m8n8.x2.shared.b16 {%0,%1}, [%2];"
                 : "=r"(r[0]), "=r"(r[1]) : "r"(addr));
}
__device__ __forceinline__ void mma16816(float* c, const uint32_t* a, const uint32_t* b) {
    asm volatile(
        "mma.sync.aligned.m16n8k16.row.col.f32.f16.f16.f32 "
        "{%0,%1,%2,%3}, {%4,%5,%6,%7}, {%8,%9}, {%0,%1,%2,%3};"
        : "+f"(c[0]), "+f"(c[1]), "+f"(c[2]), "+f"(c[3])
        : "r"(a[0]), "r"(a[1]), "r"(a[2]), "r"(a[3]), "r"(b[0]), "r"(b[1]));
}

// ---------------------------------------------------------------- prep (conv deps only)
// blocks [0,256): char emb transpose+fp16; [256,288): conv W pack
__global__ void k_prep0(const float* __restrict__ ce, const float* __restrict__ cw) {
    int b = blockIdx.x, tid = threadIdx.x;
    if (b < 256) {
        int c = b;
        for (int d = tid; d < 512; d += 256) {
            float v = (c == 0) ? 0.f : ce[c * 512 + d] * 64.f;
            g_ceh[c * 512 + (d & 31) * 16 + (d >> 5)] = __float2half(v);
        }
    } else {
        int og = (b - 256) >> 3, s = (b - 256) & 7;
        int oc = tid >> 1, half = tid & 1;
        __half* gb = (__half*)g_wA4;
        size_t base = ((size_t)og * 8 + s) * 27648;
#pragma unroll
        for (int t = 0; t < 3; t++) {
            size_t rb = base + (size_t)t * 9216 + oc * 72 + half * 32;
#pragma unroll
            for (int j = 0; j < 32; j++) {
                int i = half * 32 + j;
                float w = cw[(size_t)(og * 128 + oc) * 1536 +
                             (size_t)(s * 64 + i) * 3 + t] * 64.f;
                gb[rb + j] = __float2half(w);
            }
            if (half) {
#pragma unroll
                for (int j = 0; j < 8; j++)
                    gb[base + (size_t)t * 9216 + oc * 72 + 64 + j] = __half(0.f);
            }
        }
    }
}

// ---------------------------------------------------------------- B: HMMA conv v4
// grid (544, 4). bx<512: conv CTAs (128oc x 8 words). bx>=512: 128 prep CTAs
// doing sent-W repack + word gather, absorbed into the conv wave.
#define ABYTES3 55296
#define XBYTES3 52224
#define BUFB3   (ABYTES3 + XBYTES3)
#define NS3     8
#define CONV_SMEM (2 * BUFB3 + 1024)

__global__ __launch_bounds__(256, 1) void k_conv(
    const int* __restrict__ wic, const float* __restrict__ cb,
    const float* __restrict__ ws, const int* __restrict__ words,
    const float* __restrict__ we) {
    extern __shared__ char sm[];
    int tid = threadIdx.x;

    if (blockIdx.x >= 512) {
        int slice = (int)(blockIdx.x - 512) * 4 + blockIdx.y;   // 0..127
        // repack conv_sent_w center tap: 1M elems / 128 slices
        size_t base = (size_t)slice * 8192;
        for (int i = tid; i < 8192; i += 256) {
            size_t idx = base + i;
            g_wch[idx] = __float2half(ws[idx * 3 + 1]);
        }
        // word gather: 32 words per slice
        for (int e = tid; e < 32 * 128; e += 256) {
            int n = slice * 32 + (e >> 7);
            int t128 = e & 127;
            int w = words[n];
            float4 v = make_float4(0.f, 0.f, 0.f, 0.f);
            if (w != 0) v = ((const float4*)(we + (size_t)w * 512))[t128];
            __half2* dst = (__half2*)(g_uh + (size_t)n * 1024) + t128 * 2;
            dst[0] = __floats2half2_rn(v.x, v.y);
            dst[1] = __floats2half2_rn(v.z, v.w);
        }
        return;
    }

    uint32_t sb = smem_u32(sm);
    int lane = tid & 31, w = tid >> 5;
    int wm = w >> 2, wn = w & 3;
    int nb0 = blockIdx.x * 8;
    int og  = blockIdx.y;
    int oc0 = og * 128;
    int* cs = (int*)(sm + 2 * BUFB3);

    cs[tid] = wic[(nb0 + (tid >> 5)) * 32 + (tid & 31)];
    for (int e = tid; e < 384; e += 256) {
        int buf = e / 192, r = e % 192;
        int sub = r / 6, rem = r % 6, row = (rem >= 3) ? 33 : 0, q = rem % 3;
        *(uint4*)(sm + buf * BUFB3 + ABYTES3 + sub * 1632 + row * 48 + q * 16) =
            make_uint4(0, 0, 0, 0);
    }
    __syncthreads();

    const char* gA = (const char*)g_wA4 + (size_t)og * 8 * ABYTES3;

    auto issue = [&](int s, int b) {
        uint32_t Ab = sb + b * BUFB3;
        const char* src = gA + (size_t)s * ABYTES3;
        for (int i = tid; i < ABYTES3 / 16; i += 256)
            cp16(Ab + i * 16, src + i * 16);
        uint32_t Xb = Ab + ABYTES3;
#pragma unroll
        for (int it = 0; it < 8; it++) {
            int e = tid + it * 256;
            int sub = e >> 6, r = (e >> 1) & 31, h = e & 1;
            int ch = cs[(sub >> 2) * 32 + s * 4 + (sub & 3)];
            cp16(Xb + sub * 1632 + (r + 1) * 48 + h * 16,
                 g_ceh + ch * 512 + r * 16 + h * 8);
        }
        cp_commit();
    };

    float acc[4][8][4];
#pragma unroll
    for (int i = 0; i < 4; i++)
#pragma unroll
        for (int j = 0; j < 8; j++)
#pragma unroll
            for (int q = 0; q < 4; q++) acc[i][j][q] = 0.f;

    uint32_t aoff = (uint32_t)((lane & 15) * 144 + (lane >> 4) * 16);
    uint32_t brow = (uint32_t)(((lane >> 4) & 1) * 8 + (lane & 7));
    uint32_t bcol = (uint32_t)(((lane >> 3) & 1) * 16);

    issue(0, 0);
    issue(1, 1);
    for (int s = 0; s < NS3; s++) {
        if (s == NS3 - 1) cp_wait0(); else cp_wait1();
        __syncthreads();

        int b = s & 1;
        uint32_t Ab = sb + b * BUFB3;
        uint32_t Xb = Ab + ABYTES3;
#pragma unroll
        for (int t = 0; t < 3; t++) {
#pragma unroll
            for (int q = 0; q < 4; q++) {
                uint32_t ah[4][4];
#pragma unroll
                for (int mt = 0; mt < 4; mt++)
                    ldsm_x4(ah[mt], Ab + t * 18432 +
                            (wm * 64 + mt * 16) * 144 + q * 32 + aoff);
                uint32_t bf[4][4];
#pragma unroll
                for (int jp = 0; jp < 4; jp++) {
                    int wj = jp >> 1, lp = jp & 1;
                    uint32_t sub = (uint32_t)((wn * 2 + wj) * 4 + q);
                    ldsm_x4(bf[jp], Xb + sub * 1632 +
                            (lp * 16 + t + brow) * 48 + bcol);
                }
#pragma unroll
                for (int jp = 0; jp < 4; jp++)
#pragma unroll
                    for (int mt = 0; mt < 4; mt++) {
                        mma16816(acc[mt][jp * 2],     ah[mt], bf[jp] + 0);
                        mma16816(acc[mt][jp * 2 + 1], ah[mt], bf[jp] + 2);
                    }
            }
        }
        __syncthreads();
        if (s + 2 < NS3) issue(s + 2, b);
    }

#pragma unroll
    for (int j = 0; j < 2; j++) {
        int n = nb0 + wn * 2 + j;
#pragma unroll
        for (int mt = 0; mt < 4; mt++) {
            float m0 = -3.4e38f, m1 = -3.4e38f;
#pragma unroll
            for (int nt = j * 4; nt < j * 4 + 4; nt++) {
                m0 = fmaxf(m0, fmaxf(acc[mt][nt][0], acc[mt][nt][1]));
                m1 = fmaxf(m1, fmaxf(acc[mt][nt][2], acc[mt][nt][3]));
            }
            m0 = fmaxf(m0, __shfl_xor_sync(0xffffffffu, m0, 1));
            m0 = fmaxf(m0, __shfl_xor_sync(0xffffffffu, m0, 2));
            m1 = fmaxf(m1, __shfl_xor_sync(0xffffffffu, m1, 1));
            m1 = fmaxf(m1, __shfl_xor_sync(0xffffffffu, m1, 2));
            if ((lane & 3) == 0) {
                int row = lane >> 2;
                int oc = oc0 + wm * 64 + mt * 16 + row;
                g_uh[(size_t)n * 1024 + 512 + oc] =
                    __float2half(m0 * (1.f / 4096.f) + cb[oc]);
                g_uh[(size_t)n * 1024 + 512 + oc + 8] =
                    __float2half(m1 * (1.f / 4096.f) + cb[oc + 8]);
            }
        }
    }
}

// ---------------------------------------------------------------- C2: HMMA sent v2
// K-chunks of 64 (16 stages), pitch 144B, dynamic SMEM 2x36864 + red.
#define SENT_TILE 18432
#define SENT_BUF  (2 * SENT_TILE)
#define SENT_SMEM (2 * SENT_BUF + 2688)

__global__ __launch_bounds__(256, 2) void k_sent(const float* __restrict__ csb) {
    extern __shared__ char sms[];
    uint32_t sb = smem_u32(sms);
    float* red = (float*)(sms + 2 * SENT_BUF);
    int tid = threadIdx.x;
    int lane = tid & 31, w = tid >> 5;
    int wm = w >> 2, wn = w & 3;
    int nb = blockIdx.x * 128;
    int o0 = blockIdx.y * 128;

    auto issue = [&](int kc, int b) {
        uint32_t Ub = sb + b * SENT_BUF;
#pragma unroll
        for (int it = 0; it < 4; it++) {
            int e = tid + it * 256;            // 0..1023
            int r = e >> 3, q = e & 7;
            cp16(Ub + r * 144 + q * 16,
                 g_uh + (size_t)(nb + r) * 1024 + kc * 64 + q * 8);
        }
        uint32_t Wb = Ub + SENT_TILE;
#pragma unroll
        for (int it = 0; it < 4; it++) {
            int e = tid + it * 256;
            int r = e >> 3, q = e & 7;
            cp16(Wb + r * 144 + q * 16,
                 g_wch + (size_t)(o0 + r) * 1024 + kc * 64 + q * 8);
        }
        cp_commit();
    };

    float acc[4][4][4];
#pragma unroll
    for (int i = 0; i < 4; i++)
#pragma unroll
        for (int j = 0; j < 4; j++)
#pragma unroll
            for (int q = 0; q < 4; q++) acc[i][j][q] = 0.f;

    uint32_t aoff = (uint32_t)((wm * 64 + (lane & 15)) * 144 + (lane >> 4) * 16);
    uint32_t boff = (uint32_t)((wn * 32 + (lane & 7)) * 144 + ((lane >> 3) & 1) * 16);

    issue(0, 0);
    for (int kc = 0; kc < 16; kc++) {
        int b = kc & 1;
        if (kc < 15) { issue(kc + 1, b ^ 1); cp_wait1(); } else cp_wait0();
        __syncthreads();
        uint32_t Ub = sb + b * SENT_BUF;
        uint32_t Wb = Ub + SENT_TILE;
#pragma unroll
        for (int ks = 0; ks < 4; ks++) {
            uint32_t a[4][4];
#pragma unroll
            for (int mt = 0; mt < 4; mt++)
                ldsm_x4(a[mt], Wb + mt * 16 * 144 + ks * 32 + aoff);
            uint32_t bf[4][2];
#pragma unroll
            for (int nt = 0; nt < 4; nt++)
                ldsm_x2(bf[nt], Ub + nt * 8 * 144 + ks * 32 + boff);
#pragma unroll
            for (int nt = 0; nt < 4; nt++)
#pragma unroll
                for (int mt = 0; mt < 4; mt++)
                    mma16816(acc[mt][nt], a[mt], bf[nt]);
        }
        __syncthreads();
    }

#pragma unroll
    for (int mt = 0; mt < 4; mt++) {
        float m0 = -3.4e38f, m1 = -3.4e38f;
#pragma unroll
        for (int nt = 0; nt < 4; nt++) {
            m0 = fmaxf(m0, fmaxf(acc[mt][nt][0], acc[mt][nt][1]));
            m1 = fmaxf(m1, fmaxf(acc[mt][nt][2], acc[mt][nt][3]));
        }
        m0 = fmaxf(m0, __shfl_xor_sync(0xffffffffu, m0, 1));
        m0 = fmaxf(m0, __shfl_xor_sync(0xffffffffu, m0, 2));
        m1 = fmaxf(m1, __shfl_xor_sync(0xffffffffu, m1, 1));
        m1 = fmaxf(m1, __shfl_xor_sync(0xffffffffu, m1, 2));
        if ((lane & 3) == 0) {
            int ol = wm * 64 + mt * 16 + (lane >> 2);
            red[ol * 5 + wn]       = m0;
            red[(ol + 8) * 5 + wn] = m1;
        }
    }
    __syncthreads();
    if (tid < 128) {
        float m = fmaxf(fmaxf(red[tid * 5], red[tid * 5 + 1]),
                        fmaxf(red[tid * 5 + 2], red[tid * 5 + 3]));
        g_pmax[blockIdx.x * 1024 + o0 + tid] = m + csb[o0 + tid];
    }
}

// ---------------------------------------------------------------- D1: global max
__global__ void k_rmax() {
    int o = blockIdx.x * 128 + threadIdx.x;
    float m = g_pmax[o];
#pragma unroll
    for (int j = 1; j < 32; j++) m = fmaxf(m, g_pmax[j * 1024 + o]);
    g_rm[o] = m;
}

// ---------------------------------------------------------------- D2: lin1 + tanh
__global__ void k_lin1(const float* __restrict__ w1, const float* __restrict__ b1) {
    int lane = threadIdx.x & 31;
    int j = blockIdx.x * 4 + (threadIdx.x >> 5);
    float s = 0.f;
    const float* wr = w1 + (size_t)j * 1024;
#pragma unroll
    for (int i = 0; i < 32; i++)
        s = fmaf(g_rm[i * 32 + lane], wr[i * 32 + lane], s);
#pragma unroll
    for (int d = 16; d > 0; d >>= 1) s += __shfl_xor_sync(0xffffffffu, s, d);
    if (lane == 0) g_h[j] = tanhf(s + b1[j]);
}

// ---------------------------------------------------------------- D3: lin2
__global__ void k_lin2(const float* __restrict__ w2, const float* __restrict__ b2,
                       float* __restrict__ out) {
    __shared__ float p0s[256], p1s[256];
    int t = threadIdx.x;
    float p0 = 0.f, p1 = 0.f;
    for (int i = t; i < 2048; i += 256) {
        float h = g_h[i];
        p0 = fmaf(h, w2[i], p0);
        p1 = fmaf(h, w2[2048 + i], p1);
    }
    p0s[t] = p0; p1s[t] = p1;
    __syncthreads();
    for (int s = 128; s > 0; s >>= 1) {
        if (t < s) { p0s[t] += p0s[t + s]; p1s[t] += p1s[t + s]; }
        __syncthreads();
    }
    if (t == 0) { out[0] = p0s[0] + b2[0]; out[1] = p1s[0] + b2[1]; }
}

// ----------------------------------------------------------------
extern "C" void kernel_launch(void* const* d_in, const int* in_sizes, int n_in,
                              void* d_out, int out_size) {
    const int*   words = (const int*)d_in[0];
    const int*   wic   = (const int*)d_in[1];
    const float* we    = (const float*)d_in[2];
    const float* ce    = (const float*)d_in[3];
    const float* cw    = (const float*)d_in[4];
    const float* cb    = (const float*)d_in[5];
    const float* ws    = (const float*)d_in[6];
    const float* csb   = (const float*)d_in[7];
    const float* w1    = (const float*)d_in[8];
    const float* b1    = (const float*)d_in[9];
    const float* w2    = (const float*)d_in[10];
    const float* b2    = (const float*)d_in[11];
    float* out = (float*)d_out;

    static int smem_set = 0;
    if (!smem_set) {
        cudaFuncSetAttribute(k_conv, cudaFuncAttributeMaxDynamicSharedMemorySize,
                             CONV_SMEM);
        cudaFuncSetAttribute(k_sent, cudaFuncAttributeMaxDynamicSharedMemorySize,
                             SENT_SMEM);
        smem_set = 1;
    }

    k_prep0<<<288, 256>>>(ce, cw);
    k_conv <<<dim3(544, 4), 256, CONV_SMEM>>>(wic, cb, ws, words, we);
    k_sent <<<dim3(32, 8), 256, SENT_SMEM>>>(csb);
    k_rmax <<<8, 128>>>();
    k_lin1 <<<512, 128>>>(w1, b1);
    k_lin2 <<<1, 256>>>(w2, b2, out);
}